// round 10
// baseline (speedup 1.0000x reference)
#include <cuda_runtime.h>
#include <cuda_fp16.h>
#include <cstdint>
#include <math.h>

// Problem shapes (fixed by setup_inputs)
#define NN 40000
#define EE 100000
#define DD 768
#define GG 128
#define D3 2304
#define SS 589824                     // 768*768 elements

// ---------------- scratch (static device globals; allocation-free) ----------
__device__ static __half g_xh [(size_t)NN * DD];        // x in fp16
__device__ static __half g_h0 [(size_t)NN * DD];        // h0 / t
__device__ static __half g_emb3[(size_t)NN * D3];       // concat(h1,h2,h3)
__device__ static __half g_uv [(size_t)NN * 2 * DD];    // [u | v] per node
__device__ static __half g_yh [(size_t)GG * DD];        // y in fp16
__device__ static __half g_yp [(size_t)GG * DD];        // leaky(y@py+b)
__device__ static __half g_w  [(size_t)GG * DD];        // yp@W3 + pc1_b per graph
__device__ static __half g_wT [8257536];                // weights: 14 * 768*768 halves
__device__ static float  g_buv[2 * DD];                 // bias for uv GEMM
__device__ static float  g_zero[2 * DD];                // zero bias (zero-init)

// ---------------- helpers ----------------------------------------------------
__device__ __forceinline__ uint32_t smem_u32(const void* p) {
    uint32_t a;
    asm("{ .reg .u64 t; cvta.to.shared.u64 t, %1; cvt.u32.u64 %0, t; }" : "=r"(a) : "l"(p));
    return a;
}

__device__ __forceinline__ void cp_async16(uint32_t dst, const void* src, bool pred) {
    int sz = pred ? 16 : 0;
    asm volatile("cp.async.cg.shared.global [%0], [%1], 16, %2;"
                 :: "r"(dst), "l"(src), "r"(sz) : "memory");
}
#define CP_COMMIT() asm volatile("cp.async.commit_group;" ::: "memory")
#define CP_WAIT(n)  asm volatile("cp.async.wait_group %0;" :: "n"(n) : "memory")

__device__ __forceinline__ void ldsm_x4(uint32_t& r0, uint32_t& r1, uint32_t& r2, uint32_t& r3,
                                        uint32_t addr) {
    asm volatile("ldmatrix.sync.aligned.m8n8.x4.shared.b16 {%0,%1,%2,%3}, [%4];"
                 : "=r"(r0), "=r"(r1), "=r"(r2), "=r"(r3) : "r"(addr));
}

__device__ __forceinline__ void mma_f16(float d[4], const uint32_t a[4], const uint32_t b[2]) {
    asm volatile(
        "mma.sync.aligned.m16n8k16.row.col.f32.f16.f16.f32 "
        "{%0,%1,%2,%3}, {%4,%5,%6,%7}, {%8,%9}, {%0,%1,%2,%3};"
        : "+f"(d[0]), "+f"(d[1]), "+f"(d[2]), "+f"(d[3])
        : "r"(a[0]), "r"(a[1]), "r"(a[2]), "r"(a[3]), "r"(b[0]), "r"(b[1]));
}

#define SW(o) ((o) ^ (((o) >> 3) & 0x70))   // SW128 byte swizzle within 1KB atom

// ---------------- fp16 mma.sync GEMM tile (R5/R8 proven core) -----------------
#define BM 128
#define BN 128
#define BK 64
#define TILE_BYTES 16384                   // 128 rows * 128B
#define STAGE_BYTES (2 * TILE_BYTES)       // A then B: 32 KB
#define NSTAGE 3
#define DYN_BYTES (NSTAGE * STAGE_BYTES)   // 96 KB -> 2 CTAs/SM

__device__ __forceinline__ void gemm_tile(
    const __half* __restrict__ A, int lda,
    const __half* __restrict__ Bt,
    const float* __restrict__ bias,
    __half* __restrict__ C, int ldc,
    int M, int K, int act, int m0, int n0, char* sh)
{
    const int tid = threadIdx.x;
    const int wid = tid >> 5, lane = tid & 31;
    const int g = lane >> 2, t = lane & 3;
    const int wm = wid & 3, wn = wid >> 2;      // 4 M-warps x 2 N-warps

    const int nk = K / BK;
    const uint32_t shbase = smem_u32(sh);

    const int lrow0 = tid >> 3;           // +32*i
    const int lchB  = (tid & 7) * 16;
    const int lchH  = (tid & 7) * 8;

    auto issue_tile = [&](int kt) {
        if (kt < nk) {
            uint32_t As = shbase + (uint32_t)(kt % NSTAGE) * STAGE_BYTES;
            uint32_t Bs = As + TILE_BYTES;
            #pragma unroll
            for (int i = 0; i < 4; i++) {
                int row = lrow0 + i * 32;
                int gr = m0 + row;
                cp_async16(As + SW((uint32_t)(row * 128 + lchB)),
                           A + (long long)gr * lda + kt * BK + lchH, gr < M);
                cp_async16(Bs + SW((uint32_t)(row * 128 + lchB)),
                           Bt + (long long)(n0 + row) * K + kt * BK + lchH, true);
            }
        }
        CP_COMMIT();
    };

    float acc[2][8][4];
    #pragma unroll
    for (int i = 0; i < 2; i++)
        #pragma unroll
        for (int j = 0; j < 8; j++)
            #pragma unroll
            for (int q = 0; q < 4; q++) acc[i][j][q] = 0.f;

    issue_tile(0);
    issue_tile(1);

    const int lmRow = lane & 15;
    const int lmHi  = (lane & 16) ? 16 : 0;

    #pragma unroll 1
    for (int kt = 0; kt < nk; ++kt) {
        CP_WAIT(1);
        __syncthreads();
        issue_tile(kt + 2);

        uint32_t As = shbase + (uint32_t)(kt % NSTAGE) * STAGE_BYTES;
        uint32_t Bs = As + TILE_BYTES;

        #pragma unroll
        for (int ks = 0; ks < 4; ++ks) {
            const int kb = ks * 32 + lmHi;
            uint32_t a[2][4], b[8][2];
            #pragma unroll
            for (int mt = 0; mt < 2; ++mt) {
                int row = wm * 32 + mt * 16 + lmRow;
                ldsm_x4(a[mt][0], a[mt][1], a[mt][2], a[mt][3],
                        As + SW((uint32_t)(row * 128 + kb)));
            }
            #pragma unroll
            for (int nq = 0; nq < 4; ++nq) {
                int row = wn * 64 + nq * 16 + lmRow;
                ldsm_x4(b[2*nq][0], b[2*nq+1][0], b[2*nq][1], b[2*nq+1][1],
                        Bs + SW((uint32_t)(row * 128 + kb)));
            }
            #pragma unroll
            for (int mt = 0; mt < 2; ++mt)
                #pragma unroll
                for (int nt = 0; nt < 8; ++nt)
                    mma_f16(acc[mt][nt], a[mt], b[nt]);
        }
    }

    // ---- epilogue: bias + activation + fp16 store ----
    #pragma unroll
    for (int mt = 0; mt < 2; ++mt) {
        int row0 = m0 + wm * 32 + mt * 16 + g;
        #pragma unroll
        for (int nt = 0; nt < 8; ++nt) {
            int col = n0 + wn * 64 + nt * 8 + t * 2;
            float2 bb = *(const float2*)(bias + col);
            float v0 = acc[mt][nt][0] + bb.x;
            float v1 = acc[mt][nt][1] + bb.y;
            float v2 = acc[mt][nt][2] + bb.x;
            float v3 = acc[mt][nt][3] + bb.y;
            if (act == 1) {
                v0 = fmaxf(v0, 0.f); v1 = fmaxf(v1, 0.f);
                v2 = fmaxf(v2, 0.f); v3 = fmaxf(v3, 0.f);
            } else if (act == 2) {
                v0 = (v0 > 0.f) ? v0 : 0.4f * v0;  v1 = (v1 > 0.f) ? v1 : 0.4f * v1;
                v2 = (v2 > 0.f) ? v2 : 0.4f * v2;  v3 = (v3 > 0.f) ? v3 : 0.4f * v3;
            }
            if (row0 < M)
                *(__half2*)(C + (long long)row0 * ldc + col) =
                    __float22half2_rn(make_float2(v0, v1));
            if (row0 + 8 < M)
                *(__half2*)(C + (long long)(row0 + 8) * ldc + col) =
                    __float22half2_rn(make_float2(v2, v3));
        }
    }
}

// ---------------- multi-GEMM launch: up to 3 independent block ranges ---------
struct GemmDesc {
    const __half* A; const __half* Bt; __half* C;
    const float* bias;
    int lda, ldc, M, K, act, nN, nBlk;
};

__global__ __launch_bounds__(256) void gemm_multi(GemmDesc d0, GemmDesc d1, GemmDesc d2)
{
    extern __shared__ char sh[];
    int bid = blockIdx.x;
    GemmDesc d;
    if (bid < d0.nBlk)                 { d = d0; }
    else if (bid < d0.nBlk + d1.nBlk)  { d = d1; bid -= d0.nBlk; }
    else                               { d = d2; bid -= d0.nBlk + d1.nBlk; }
    int n = bid % d.nN, m = bid / d.nN;
    gemm_tile(d.A, d.lda, d.Bt, d.bias, d.C, d.ldc, d.M, d.K, d.act,
              m * BM, n * BN, sh);
}

// ---------------- fused prep: converts + transposes + bias_uv -----------------
// Range decode (1-D grid):
//  [0, 30672)            convert x|y|o2W fp32->fp16 (float4 granularity)
//  [30672, 35280)        8x 768x768 transpose (576 blocks each)
//  [35280, 37008)        o1 transpose (24 n x 72 k)
//  [37008, 37014)        bias_uv direct from fp32 pc1_W / o2_b
#define PF_CVT  30672
#define PF_T8   4608
#define PF_TO1  1728
#define PF_BUV  6
#define PF_TOTAL (PF_CVT + PF_T8 + PF_TO1 + PF_BUV)

struct PrepPack {
    const float* x; const float* y; const float* o2W;
    const float* w8[8];                  // ah,c0,c1,c2,py,W1,W2,W3
    const float* o1W;
    const float* pc1W; const float* o2b;
};

__global__ __launch_bounds__(256) void prep_fused(PrepPack P)
{
    __shared__ float tb[32][33];
    const int bid = blockIdx.x;
    const int tid = threadIdx.x;

    if (bid < PF_CVT) {
        // flat convert of [x | y | o2W]
        const long long nx = (long long)NN * DD;
        const long long ny = (long long)GG * DD;
        const long long nw = (long long)DD * DD;
        long long i = ((long long)bid * 256 + tid) * 4;
        const float* src; __half* dst; long long j;
        if (i < nx) { src = P.x; dst = g_xh; j = i; }
        else if (i < nx + ny) { src = P.y; dst = g_yh; j = i - nx; }
        else if (i < nx + ny + nw) { src = P.o2W; dst = g_wT + 13 * (size_t)SS; j = i - nx - ny; }
        else return;
        float4 v = *(const float4*)(src + j);
        *(__half2*)(dst + j)     = __float22half2_rn(make_float2(v.x, v.y));
        *(__half2*)(dst + j + 2) = __float22half2_rn(make_float2(v.z, v.w));
    } else if (bid < PF_CVT + PF_T8) {
        int idx = bid - PF_CVT;
        int z = idx / 576, rem = idx % 576;
        const float* W = P.w8[z];
        __half* Wt = g_wT + (size_t)z * SS;
        int n0 = (rem % 24) * 32, k0 = (rem / 24) * 32;
        int xq = tid & 31, yq = tid >> 5;
        #pragma unroll
        for (int i = 0; i < 32; i += 8)
            tb[yq + i][xq] = W[(long long)(k0 + yq + i) * DD + n0 + xq];
        __syncthreads();
        #pragma unroll
        for (int i = 0; i < 32; i += 8)
            Wt[(long long)(n0 + yq + i) * DD + k0 + xq] = __float2half_rn(tb[xq][yq + i]);
    } else if (bid < PF_CVT + PF_T8 + PF_TO1) {
        int idx = bid - PF_CVT - PF_T8;
        __half* Wt = g_wT + 8 * (size_t)SS;
        int n0 = (idx % 24) * 32, k0 = (idx / 24) * 32;
        int xq = tid & 31, yq = tid >> 5;
        #pragma unroll
        for (int i = 0; i < 32; i += 8)
            tb[yq + i][xq] = P.o1W[(long long)(k0 + yq + i) * DD + n0 + xq];
        __syncthreads();
        #pragma unroll
        for (int i = 0; i < 32; i += 8)
            Wt[(long long)(n0 + yq + i) * D3 + k0 + xq] = __float2half_rn(tb[xq][yq + i]);
    } else {
        // bias_uv: b_uv[n] = sum_k o2_b[k] * pc1_W[(w2ofs + k)*768 + n']
        int n = (bid - PF_CVT - PF_T8 - PF_TO1) * 256 + tid;   // 0..1535
        int np = (n < DD) ? n : (n - DD);
        const float* Wcol = P.pc1W + ((n < DD) ? 0 : (size_t)DD * DD) + np;
        float s = 0.f;
        #pragma unroll 4
        for (int k = 0; k < DD; k++)
            s = fmaf(P.o2b[k], Wcol[(size_t)k * DD], s);
        g_buv[n] = s;
    }
}

// ---------------- fused edge head ---------------------------------------------
__global__ __launch_bounds__(256) void edge_head(
    const __half* __restrict__ uv, const __half* __restrict__ w,
    const int* __restrict__ edge_index, const int* __restrict__ batch,
    const float* __restrict__ pc2W /*[768,2]*/, const float* __restrict__ b2,
    const float* __restrict__ lab, float* __restrict__ out, int E)
{
    __shared__ float w0[DD];
    __shared__ float w1[DD];
    for (int i = threadIdx.x; i < DD; i += blockDim.x) {
        w0[i] = pc2W[2 * i];
        w1[i] = pc2W[2 * i + 1];
    }
    __syncthreads();

    int warp = threadIdx.x >> 5;
    int lane = threadIdx.x & 31;
    int e = blockIdx.x * 8 + warp;
    if (e >= E) return;

    int src = edge_index[e];
    int dst = edge_index[E + e];
    int gph = batch[src];

    const __half2* ur = (const __half2*)(uv + (long long)src * (2 * DD));
    const __half2* vr = (const __half2*)(uv + (long long)dst * (2 * DD) + DD);
    const __half2* wr = (const __half2*)(w  + (long long)gph * DD);

    float a0 = 0.f, a1 = 0.f;
    #pragma unroll
    for (int i = 0; i < 12; i++) {
        int k = lane + i * 32;
        float2 fu = __half22float2(ur[k]);
        float2 fv = __half22float2(vr[k]);
        float2 fw = __half22float2(wr[k]);
        float q0 = fmaxf(fu.x + fv.x + fw.x, 0.f);
        float q1 = fmaxf(fu.y + fv.y + fw.y, 0.f);
        a0 = fmaf(q0, w0[2*k], a0);   a0 = fmaf(q1, w0[2*k+1], a0);
        a1 = fmaf(q0, w1[2*k], a1);   a1 = fmaf(q1, w1[2*k+1], a1);
    }
    #pragma unroll
    for (int off = 16; off > 0; off >>= 1) {
        a0 += __shfl_xor_sync(0xffffffffu, a0, off);
        a1 += __shfl_xor_sync(0xffffffffu, a1, off);
    }
    if (lane == 0) {
        out[2 * e]     = 1.f / (1.f + expf(-(a0 + b2[0])));
        out[2 * e + 1] = 1.f / (1.f + expf(-(a1 + b2[1])));
        out[2 * E + e] = lab[e];
    }
}

// ---------------- host launch ------------------------------------------------
static __half *p_xh = nullptr, *p_h0 = nullptr, *p_emb3 = nullptr, *p_uv = nullptr,
              *p_yh = nullptr, *p_yp = nullptr, *p_w = nullptr, *p_wT = nullptr;
static float  *p_buv = nullptr, *p_zero = nullptr;

static GemmDesc mkdesc(const __half* A, int lda, const __half* Bt, const float* bias,
                       __half* C, int ldc, int M, int K, int act) {
    GemmDesc d;
    d.A = A; d.lda = lda; d.Bt = Bt; d.bias = bias; d.C = C; d.ldc = ldc;
    d.M = M; d.K = K; d.act = act;
    d.nN = 0; d.nBlk = 0;
    return d;
}

extern "C" void kernel_launch(void* const* d_in, const int* in_sizes, int n_in,
                              void* d_out, int out_size)
{
    if (!p_wT) {  // one-time setup on the (uncaptured) correctness call
        cudaGetSymbolAddress((void**)&p_xh,   g_xh);
        cudaGetSymbolAddress((void**)&p_h0,   g_h0);
        cudaGetSymbolAddress((void**)&p_emb3, g_emb3);
        cudaGetSymbolAddress((void**)&p_uv,   g_uv);
        cudaGetSymbolAddress((void**)&p_yh,   g_yh);
        cudaGetSymbolAddress((void**)&p_yp,   g_yp);
        cudaGetSymbolAddress((void**)&p_w,    g_w);
        cudaGetSymbolAddress((void**)&p_wT,   g_wT);
        cudaGetSymbolAddress((void**)&p_buv,  g_buv);
        cudaGetSymbolAddress((void**)&p_zero, g_zero);
        cudaFuncSetAttribute(gemm_multi,
                             cudaFuncAttributeMaxDynamicSharedMemorySize, DYN_BYTES);
    }

    const float* x          = (const float*)d_in[0];
    const int*   edge_index = (const int*  )d_in[1];
    const int*   batch      = (const int*  )d_in[2];
    const float* y          = (const float*)d_in[5];
    const float* edge_label = (const float*)d_in[6];
    const float* ah_W  = (const float*)d_in[7];
    const float* ah_b  = (const float*)d_in[8];
    const float* c0_W  = (const float*)d_in[9];
    const float* c0_b  = (const float*)d_in[10];
    const float* c1_W  = (const float*)d_in[11];
    const float* c1_b  = (const float*)d_in[12];
    const float* c2_W  = (const float*)d_in[13];
    const float* c2_b  = (const float*)d_in[14];
    const float* o1_W  = (const float*)d_in[15];
    const float* o1_b  = (const float*)d_in[16];
    const float* o2_W  = (const float*)d_in[17];
    const float* o2_b  = (const float*)d_in[18];
    const float* py_W  = (const float*)d_in[19];
    const float* py_b  = (const float*)d_in[20];
    const float* pc1_W = (const float*)d_in[21];
    const float* pc1_b = (const float*)d_in[22];
    const float* pc2_W = (const float*)d_in[23];
    const float* pc2_b = (const float*)d_in[24];

    float* out = (float*)d_out;

    // weight slots in g_wT (halves):
    // 0 ah | 1 c0 | 2 c1 | 3 c2 | 4 py | 5 W1 | 6 W2 | 7 W3 | 8..10 o1 | 11..12 uv | 13 o2h
    __half* wt_ah = p_wT;
    __half* wt_c0 = p_wT + (size_t)SS;
    __half* wt_c1 = p_wT + 2 * (size_t)SS;
    __half* wt_c2 = p_wT + 3 * (size_t)SS;
    __half* wt_py = p_wT + 4 * (size_t)SS;
    __half* wt_W12 = p_wT + 5 * (size_t)SS;
    __half* wt_W3 = p_wT + 7 * (size_t)SS;
    __half* wt_o1 = p_wT + 8 * (size_t)SS;
    __half* wt_uv = p_wT + 11 * (size_t)SS;
    __half* o2h   = p_wT + 13 * (size_t)SS;

    // ---- prep: one fused launch ----
    PrepPack P;
    P.x = x; P.y = y; P.o2W = o2_W;
    P.w8[0] = ah_W; P.w8[1] = c0_W; P.w8[2] = c1_W; P.w8[3] = c2_W;
    P.w8[4] = py_W;
    P.w8[5] = pc1_W;                  // W1
    P.w8[6] = pc1_W + 768 * DD;       // W2
    P.w8[7] = pc1_W + 1536 * DD;      // W3
    P.o1W = o1_W; P.pc1W = pc1_W; P.o2b = o2_b;
    prep_fused<<<PF_TOTAL, 256>>>(P);

    const int MB = (NN + BM - 1) / BM;   // 313
    GemmDesc dz = mkdesc(nullptr, 0, nullptr, nullptr, nullptr, 0, 0, BK, 0);

    // ---- launch 2: ah (1878) + composite uv-weights (72) + yp (6) ----
    {
        GemmDesc dAH = mkdesc(p_xh, DD, wt_ah, ah_b, p_h0, DD, NN, DD, 1);
        dAH.nN = 6;  dAH.nBlk = 6 * MB;
        GemmDesc dLC = mkdesc(wt_W12, DD, o2h, p_zero, wt_uv, DD, 2 * DD, DD, 0);
        dLC.nN = 6;  dLC.nBlk = 72;
        GemmDesc dYP = mkdesc(p_yh, DD, wt_py, py_b, p_yp, DD, GG, DD, 2);
        dYP.nN = 6;  dYP.nBlk = 6;
        gemm_multi<<<dAH.nBlk + dLC.nBlk + dYP.nBlk, 256, DYN_BYTES>>>(dAH, dLC, dYP);
    }
    // ---- launch 3: c0 (1878) + w (6) ----
    {
        GemmDesc dC0 = mkdesc(p_h0, DD, wt_c0, c0_b, p_emb3, D3, NN, DD, 1);
        dC0.nN = 6;  dC0.nBlk = 6 * MB;
        GemmDesc dW = mkdesc(p_yp, DD, wt_W3, pc1_b, p_w, DD, GG, DD, 0);
        dW.nN = 6;   dW.nBlk = 6;
        gemm_multi<<<dC0.nBlk + dW.nBlk, 256, DYN_BYTES>>>(dC0, dW, dz);
    }
    // ---- launches 4-7: c1, c2, o1, uv ----
    {
        GemmDesc d = mkdesc(p_emb3, D3, wt_c1, c1_b, p_emb3 + DD, D3, NN, DD, 1);
        d.nN = 6; d.nBlk = 6 * MB;
        gemm_multi<<<d.nBlk, 256, DYN_BYTES>>>(d, dz, dz);
    }
    {
        GemmDesc d = mkdesc(p_emb3 + DD, D3, wt_c2, c2_b, p_emb3 + 2 * DD, D3, NN, DD, 1);
        d.nN = 6; d.nBlk = 6 * MB;
        gemm_multi<<<d.nBlk, 256, DYN_BYTES>>>(d, dz, dz);
    }
    {
        GemmDesc d = mkdesc(p_emb3, D3, wt_o1, o1_b, p_h0, DD, NN, D3, 1);
        d.nN = 6; d.nBlk = 6 * MB;
        gemm_multi<<<d.nBlk, 256, DYN_BYTES>>>(d, dz, dz);
    }
    {
        GemmDesc d = mkdesc(p_h0, DD, wt_uv, p_buv, p_uv, 2 * DD, NN, DD, 0);
        d.nN = 12; d.nBlk = 12 * MB;
        gemm_multi<<<d.nBlk, 256, DYN_BYTES>>>(d, dz, dz);
    }

    // ---- launch 8: fused edge head ----
    edge_head<<<(EE + 7) / 8, 256>>>(p_uv, p_w, edge_index, batch,
                                     pc2_W, pc2_b, edge_label, out, EE);

    (void)n_in; (void)in_sizes; (void)out_size;
}

// round 11
// speedup vs baseline: 1.1251x; 1.1251x over previous
#include <cuda_runtime.h>
#include <cuda_fp16.h>
#include <cstdint>
#include <math.h>

// Problem shapes (fixed by setup_inputs)
#define NN 40000
#define EE 100000
#define DD 768
#define GG 128
#define D3 2304
#define SS 589824                     // 768*768 elements

// ---------------- scratch (static device globals; allocation-free) ----------
__device__ static __half g_xh [(size_t)NN * DD];        // x in fp16
__device__ static __half g_h0 [(size_t)NN * DD];        // h0 / t
__device__ static __half g_emb3[(size_t)NN * D3];       // concat(h1,h2,h3)
__device__ static __half g_uv [(size_t)NN * 2 * DD];    // [u | v] per node
__device__ static __half g_yh [(size_t)GG * DD];        // y in fp16
__device__ static __half g_yp [(size_t)GG * DD];        // leaky(y@py+b)
__device__ static __half g_w  [(size_t)GG * DD];        // yp@W3 + pc1_b per graph
__device__ static __half g_wT [8257536];                // weights: 14 * 768*768 halves
__device__ static float  g_buv[2 * DD];                 // bias for uv GEMM
__device__ static float  g_zero[2 * DD];                // zero bias (zero-init)

// ---------------- helpers ----------------------------------------------------
__device__ __forceinline__ uint32_t smem_u32(const void* p) {
    uint32_t a;
    asm("{ .reg .u64 t; cvta.to.shared.u64 t, %1; cvt.u32.u64 %0, t; }" : "=r"(a) : "l"(p));
    return a;
}

__device__ __forceinline__ void cp_async16(uint32_t dst, const void* src, bool pred) {
    int sz = pred ? 16 : 0;
    asm volatile("cp.async.cg.shared.global [%0], [%1], 16, %2;"
                 :: "r"(dst), "l"(src), "r"(sz) : "memory");
}
#define CP_COMMIT() asm volatile("cp.async.commit_group;" ::: "memory")
#define CP_WAIT(n)  asm volatile("cp.async.wait_group %0;" :: "n"(n) : "memory")

__device__ __forceinline__ void ldsm_x4(uint32_t& r0, uint32_t& r1, uint32_t& r2, uint32_t& r3,
                                        uint32_t addr) {
    asm volatile("ldmatrix.sync.aligned.m8n8.x4.shared.b16 {%0,%1,%2,%3}, [%4];"
                 : "=r"(r0), "=r"(r1), "=r"(r2), "=r"(r3) : "r"(addr));
}

__device__ __forceinline__ void mma_f16(float d[4], const uint32_t a[4], const uint32_t b[2]) {
    asm volatile(
        "mma.sync.aligned.m16n8k16.row.col.f32.f16.f16.f32 "
        "{%0,%1,%2,%3}, {%4,%5,%6,%7}, {%8,%9}, {%0,%1,%2,%3};"
        : "+f"(d[0]), "+f"(d[1]), "+f"(d[2]), "+f"(d[3])
        : "r"(a[0]), "r"(a[1]), "r"(a[2]), "r"(a[3]), "r"(b[0]), "r"(b[1]));
}

#define SW(o) ((o) ^ (((o) >> 3) & 0x70))   // SW128 byte swizzle within 1KB atom

// ---------------- fp16 mma.sync GEMM (R5/R8 proven config) --------------------
// C[M,N] = act(A[M,K] @ Bt[N,K]^T + bias),  A/Bt/C fp16, bias fp32, accum fp32.
// BM=128, BN=128, BK=64 halves (128B rows, SW128). 8 warps: 4M x 2N (32x64 tile).
#define BM 128
#define BN 128
#define BK 64
#define TILE_BYTES 16384                   // 128 rows * 128B
#define STAGE_BYTES (2 * TILE_BYTES)       // A then B: 32 KB
#define NSTAGE 3
#define DYN_BYTES (NSTAGE * STAGE_BYTES)   // 96 KB -> 2 CTAs/SM

__global__ __launch_bounds__(256, 2) void mma_gemm(
    const __half* __restrict__ A, int lda,
    const __half* __restrict__ Bt,
    const float* __restrict__ bias,
    __half* __restrict__ C, int ldc,
    int M, int K, int act)
{
    extern __shared__ char sh[];

    const int tid = threadIdx.x;
    const int wid = tid >> 5, lane = tid & 31;
    const int g = lane >> 2, t = lane & 3;
    const int wm = wid & 3, wn = wid >> 2;      // 4 M-warps x 2 N-warps
    const int m0 = blockIdx.y * BM;
    const int n0 = blockIdx.x * BN;

    const int nk = K / BK;
    const uint32_t shbase = smem_u32(sh);

    const int lrow0 = tid >> 3;           // +32*i
    const int lchB  = (tid & 7) * 16;
    const int lchH  = (tid & 7) * 8;

    auto issue_tile = [&](int kt) {
        if (kt < nk) {
            uint32_t As = shbase + (uint32_t)(kt % NSTAGE) * STAGE_BYTES;
            uint32_t Bs = As + TILE_BYTES;
            #pragma unroll
            for (int i = 0; i < 4; i++) {
                int row = lrow0 + i * 32;
                int gr = m0 + row;
                cp_async16(As + SW((uint32_t)(row * 128 + lchB)),
                           A + (long long)gr * lda + kt * BK + lchH, gr < M);
                cp_async16(Bs + SW((uint32_t)(row * 128 + lchB)),
                           Bt + (long long)(n0 + row) * K + kt * BK + lchH, true);
            }
        }
        CP_COMMIT();
    };

    float acc[2][8][4];
    #pragma unroll
    for (int i = 0; i < 2; i++)
        #pragma unroll
        for (int j = 0; j < 8; j++)
            #pragma unroll
            for (int q = 0; q < 4; q++) acc[i][j][q] = 0.f;

    issue_tile(0);
    issue_tile(1);

    const int lmRow = lane & 15;
    const int lmHi  = (lane & 16) ? 16 : 0;

    #pragma unroll 1
    for (int kt = 0; kt < nk; ++kt) {
        CP_WAIT(1);
        __syncthreads();
        issue_tile(kt + 2);

        uint32_t As = shbase + (uint32_t)(kt % NSTAGE) * STAGE_BYTES;
        uint32_t Bs = As + TILE_BYTES;

        #pragma unroll
        for (int ks = 0; ks < 4; ++ks) {
            const int kb = ks * 32 + lmHi;
            uint32_t a[2][4], b[8][2];
            #pragma unroll
            for (int mt = 0; mt < 2; ++mt) {
                int row = wm * 32 + mt * 16 + lmRow;
                ldsm_x4(a[mt][0], a[mt][1], a[mt][2], a[mt][3],
                        As + SW((uint32_t)(row * 128 + kb)));
            }
            #pragma unroll
            for (int nq = 0; nq < 4; ++nq) {
                int row = wn * 64 + nq * 16 + lmRow;
                ldsm_x4(b[2*nq][0], b[2*nq+1][0], b[2*nq][1], b[2*nq+1][1],
                        Bs + SW((uint32_t)(row * 128 + kb)));
            }
            #pragma unroll
            for (int mt = 0; mt < 2; ++mt)
                #pragma unroll
                for (int nt = 0; nt < 8; ++nt)
                    mma_f16(acc[mt][nt], a[mt], b[nt]);
        }
    }

    // ---- epilogue: bias + activation + fp16 store ----
    #pragma unroll
    for (int mt = 0; mt < 2; ++mt) {
        int row0 = m0 + wm * 32 + mt * 16 + g;
        #pragma unroll
        for (int nt = 0; nt < 8; ++nt) {
            int col = n0 + wn * 64 + nt * 8 + t * 2;
            float2 bb = *(const float2*)(bias + col);
            float v0 = acc[mt][nt][0] + bb.x;
            float v1 = acc[mt][nt][1] + bb.y;
            float v2 = acc[mt][nt][2] + bb.x;
            float v3 = acc[mt][nt][3] + bb.y;
            if (act == 1) {
                v0 = fmaxf(v0, 0.f); v1 = fmaxf(v1, 0.f);
                v2 = fmaxf(v2, 0.f); v3 = fmaxf(v3, 0.f);
            } else if (act == 2) {
                v0 = (v0 > 0.f) ? v0 : 0.4f * v0;  v1 = (v1 > 0.f) ? v1 : 0.4f * v1;
                v2 = (v2 > 0.f) ? v2 : 0.4f * v2;  v3 = (v3 > 0.f) ? v3 : 0.4f * v3;
            }
            if (row0 < M)
                *(__half2*)(C + (long long)row0 * ldc + col) =
                    __float22half2_rn(make_float2(v0, v1));
            if (row0 + 8 < M)
                *(__half2*)(C + (long long)(row0 + 8) * ldc + col) =
                    __float22half2_rn(make_float2(v2, v3));
        }
    }
}

// ---------------- fused prep: converts + transposes + bias_uv -----------------
// Range decode (1-D grid):
//  [0, 30672)            convert x|y|o2W fp32->fp16 (float4 granularity)
//  [30672, 35280)        8x 768x768 transpose (576 blocks each)
//  [35280, 37008)        o1 transpose (24 n x 72 k)
//  [37008, 37014)        bias_uv direct from fp32 pc1_W / o2_b
#define PF_CVT  30672
#define PF_T8   4608
#define PF_TO1  1728
#define PF_BUV  6
#define PF_TOTAL (PF_CVT + PF_T8 + PF_TO1 + PF_BUV)

struct PrepPack {
    const float* x; const float* y; const float* o2W;
    const float* w8[8];                  // ah,c0,c1,c2,py,W1,W2,W3
    const float* o1W;
    const float* pc1W; const float* o2b;
};

__global__ __launch_bounds__(256) void prep_fused(PrepPack P)
{
    __shared__ float tb[32][33];
    const int bid = blockIdx.x;
    const int tid = threadIdx.x;

    if (bid < PF_CVT) {
        // flat convert of [x | y | o2W]
        const long long nx = (long long)NN * DD;
        const long long ny = (long long)GG * DD;
        const long long nw = (long long)DD * DD;
        long long i = ((long long)bid * 256 + tid) * 4;
        const float* src; __half* dst; long long j;
        if (i < nx) { src = P.x; dst = g_xh; j = i; }
        else if (i < nx + ny) { src = P.y; dst = g_yh; j = i - nx; }
        else if (i < nx + ny + nw) { src = P.o2W; dst = g_wT + 13 * (size_t)SS; j = i - nx - ny; }
        else return;
        float4 v = *(const float4*)(src + j);
        *(__half2*)(dst + j)     = __float22half2_rn(make_float2(v.x, v.y));
        *(__half2*)(dst + j + 2) = __float22half2_rn(make_float2(v.z, v.w));
    } else if (bid < PF_CVT + PF_T8) {
        int idx = bid - PF_CVT;
        int z = idx / 576, rem = idx % 576;
        const float* W = P.w8[z];
        __half* Wt = g_wT + (size_t)z * SS;
        int n0 = (rem % 24) * 32, k0 = (rem / 24) * 32;
        int xq = tid & 31, yq = tid >> 5;
        #pragma unroll
        for (int i = 0; i < 32; i += 8)
            tb[yq + i][xq] = W[(long long)(k0 + yq + i) * DD + n0 + xq];
        __syncthreads();
        #pragma unroll
        for (int i = 0; i < 32; i += 8)
            Wt[(long long)(n0 + yq + i) * DD + k0 + xq] = __float2half_rn(tb[xq][yq + i]);
    } else if (bid < PF_CVT + PF_T8 + PF_TO1) {
        int idx = bid - PF_CVT - PF_T8;
        __half* Wt = g_wT + 8 * (size_t)SS;
        int n0 = (idx % 24) * 32, k0 = (idx / 24) * 32;
        int xq = tid & 31, yq = tid >> 5;
        #pragma unroll
        for (int i = 0; i < 32; i += 8)
            tb[yq + i][xq] = P.o1W[(long long)(k0 + yq + i) * DD + n0 + xq];
        __syncthreads();
        #pragma unroll
        for (int i = 0; i < 32; i += 8)
            Wt[(long long)(n0 + yq + i) * D3 + k0 + xq] = __float2half_rn(tb[xq][yq + i]);
    } else {
        // bias_uv: b_uv[n] = sum_k o2_b[k] * pc1_W[k-th row of W1|W2][n']
        int n = (bid - PF_CVT - PF_T8 - PF_TO1) * 256 + tid;   // 0..1535
        if (n >= 2 * DD) return;
        int np = (n < DD) ? n : (n - DD);
        const float* Wcol = P.pc1W + ((n < DD) ? 0 : (size_t)DD * DD) + np;
        float s = 0.f;
        #pragma unroll 4
        for (int k = 0; k < DD; k++)
            s = fmaf(P.o2b[k], Wcol[(size_t)k * DD], s);
        g_buv[n] = s;
    }
}

// ---------------- fused edge head ---------------------------------------------
// per edge: q = relu(u[src] + v[dst] + w[batch[src]]); pred = sigmoid(q@pc2 + b2)
__global__ __launch_bounds__(256) void edge_head(
    const __half* __restrict__ uv, const __half* __restrict__ w,
    const int* __restrict__ edge_index, const int* __restrict__ batch,
    const float* __restrict__ pc2W /*[768,2]*/, const float* __restrict__ b2,
    const float* __restrict__ lab, float* __restrict__ out, int E)
{
    __shared__ float w0[DD];
    __shared__ float w1[DD];
    for (int i = threadIdx.x; i < DD; i += blockDim.x) {
        w0[i] = pc2W[2 * i];
        w1[i] = pc2W[2 * i + 1];
    }
    __syncthreads();

    int warp = threadIdx.x >> 5;
    int lane = threadIdx.x & 31;
    int e = blockIdx.x * 8 + warp;
    if (e >= E) return;

    int src = edge_index[e];
    int dst = edge_index[E + e];
    int gph = batch[src];

    const __half2* ur = (const __half2*)(uv + (long long)src * (2 * DD));
    const __half2* vr = (const __half2*)(uv + (long long)dst * (2 * DD) + DD);
    const __half2* wr = (const __half2*)(w  + (long long)gph * DD);

    float a0 = 0.f, a1 = 0.f;
    #pragma unroll
    for (int i = 0; i < 12; i++) {
        int k = lane + i * 32;               // half2 index, 0..383
        float2 fu = __half22float2(ur[k]);
        float2 fv = __half22float2(vr[k]);
        float2 fw = __half22float2(wr[k]);
        float q0 = fmaxf(fu.x + fv.x + fw.x, 0.f);
        float q1 = fmaxf(fu.y + fv.y + fw.y, 0.f);
        a0 = fmaf(q0, w0[2*k], a0);   a0 = fmaf(q1, w0[2*k+1], a0);
        a1 = fmaf(q0, w1[2*k], a1);   a1 = fmaf(q1, w1[2*k+1], a1);
    }
    #pragma unroll
    for (int off = 16; off > 0; off >>= 1) {
        a0 += __shfl_xor_sync(0xffffffffu, a0, off);
        a1 += __shfl_xor_sync(0xffffffffu, a1, off);
    }
    if (lane == 0) {
        out[2 * e]     = 1.f / (1.f + expf(-(a0 + b2[0])));
        out[2 * e + 1] = 1.f / (1.f + expf(-(a1 + b2[1])));
        out[2 * E + e] = lab[e];
    }
}

// ---------------- host launch ------------------------------------------------
static __half *p_xh = nullptr, *p_h0 = nullptr, *p_emb3 = nullptr, *p_uv = nullptr,
              *p_yh = nullptr, *p_yp = nullptr, *p_w = nullptr, *p_wT = nullptr;
static float  *p_buv = nullptr, *p_zero = nullptr;

extern "C" void kernel_launch(void* const* d_in, const int* in_sizes, int n_in,
                              void* d_out, int out_size)
{
    if (!p_wT) {  // one-time setup on the (uncaptured) correctness call
        cudaGetSymbolAddress((void**)&p_xh,   g_xh);
        cudaGetSymbolAddress((void**)&p_h0,   g_h0);
        cudaGetSymbolAddress((void**)&p_emb3, g_emb3);
        cudaGetSymbolAddress((void**)&p_uv,   g_uv);
        cudaGetSymbolAddress((void**)&p_yh,   g_yh);
        cudaGetSymbolAddress((void**)&p_yp,   g_yp);
        cudaGetSymbolAddress((void**)&p_w,    g_w);
        cudaGetSymbolAddress((void**)&p_wT,   g_wT);
        cudaGetSymbolAddress((void**)&p_buv,  g_buv);
        cudaGetSymbolAddress((void**)&p_zero, g_zero);
        cudaFuncSetAttribute(mma_gemm,
                             cudaFuncAttributeMaxDynamicSharedMemorySize, DYN_BYTES);
    }

    const float* x          = (const float*)d_in[0];
    const int*   edge_index = (const int*  )d_in[1];
    const int*   batch      = (const int*  )d_in[2];
    const float* y          = (const float*)d_in[5];
    const float* edge_label = (const float*)d_in[6];
    const float* ah_W  = (const float*)d_in[7];
    const float* ah_b  = (const float*)d_in[8];
    const float* c0_W  = (const float*)d_in[9];
    const float* c0_b  = (const float*)d_in[10];
    const float* c1_W  = (const float*)d_in[11];
    const float* c1_b  = (const float*)d_in[12];
    const float* c2_W  = (const float*)d_in[13];
    const float* c2_b  = (const float*)d_in[14];
    const float* o1_W  = (const float*)d_in[15];
    const float* o1_b  = (const float*)d_in[16];
    const float* o2_W  = (const float*)d_in[17];
    const float* o2_b  = (const float*)d_in[18];
    const float* py_W  = (const float*)d_in[19];
    const float* py_b  = (const float*)d_in[20];
    const float* pc1_W = (const float*)d_in[21];
    const float* pc1_b = (const float*)d_in[22];
    const float* pc2_W = (const float*)d_in[23];
    const float* pc2_b = (const float*)d_in[24];

    float* out = (float*)d_out;

    // weight slots in g_wT (halves):
    // 0 ah | 1 c0 | 2 c1 | 3 c2 | 4 py | 5 W1 | 6 W2 | 7 W3 | 8..10 o1 | 11..12 uv | 13 o2h
    __half* wt_ah  = p_wT;
    __half* wt_c0  = p_wT + (size_t)SS;
    __half* wt_c1  = p_wT + 2 * (size_t)SS;
    __half* wt_c2  = p_wT + 3 * (size_t)SS;
    __half* wt_py  = p_wT + 4 * (size_t)SS;
    __half* wt_W12 = p_wT + 5 * (size_t)SS;     // W1|W2 contiguous (M=1536)
    __half* wt_W3  = p_wT + 7 * (size_t)SS;
    __half* wt_o1  = p_wT + 8 * (size_t)SS;     // [768, 2304]
    __half* wt_uv  = p_wT + 11 * (size_t)SS;    // composite [1536, 768]
    __half* o2h    = p_wT + 13 * (size_t)SS;    // o2_W fp16 row-major

    // ---- prep: one fused launch ----
    PrepPack P;
    P.x = x; P.y = y; P.o2W = o2_W;
    P.w8[0] = ah_W; P.w8[1] = c0_W; P.w8[2] = c1_W; P.w8[3] = c2_W;
    P.w8[4] = py_W;
    P.w8[5] = pc1_W;                  // W1
    P.w8[6] = pc1_W + 768 * DD;       // W2
    P.w8[7] = pc1_W + 1536 * DD;      // W3
    P.o1W = o1_W; P.pc1W = pc1_W; P.o2b = o2_b;
    prep_fused<<<PF_TOTAL, 256>>>(P);

    // composite weights, single launch: rows 0..767 from W1, 768..1535 from W2
    {
        dim3 gC(DD / BN, 2 * DD / BM);    // 6 x 12
        mma_gemm<<<gC, 256, DYN_BYTES>>>(wt_W12, DD, o2h, p_zero, wt_uv, DD, 2 * DD, DD, 0);
    }

    dim3 blk(256);
    dim3 gN(DD / BN, (NN + BM - 1) / BM);        // 6 x 313
    dim3 gUV(2 * DD / BN, (NN + BM - 1) / BM);   // 12 x 313
    dim3 gG(DD / BN, 1);

    // Encoder
    mma_gemm<<<gN, blk, DYN_BYTES>>>(p_xh, DD, wt_ah, ah_b, p_h0, DD, NN, DD, 1);
    mma_gemm<<<gN, blk, DYN_BYTES>>>(p_h0, DD, wt_c0, c0_b, p_emb3, D3, NN, DD, 1);
    mma_gemm<<<gN, blk, DYN_BYTES>>>(p_emb3, D3, wt_c1, c1_b, p_emb3 + DD, D3, NN, DD, 1);
    mma_gemm<<<gN, blk, DYN_BYTES>>>(p_emb3 + DD, D3, wt_c2, c2_b, p_emb3 + 2 * DD, D3, NN, DD, 1);
    mma_gemm<<<gN, blk, DYN_BYTES>>>(p_emb3, D3, wt_o1, o1_b, p_h0, DD, NN, D3, 1);
    // uv = t @ [o2W*W1 | o2W*W2] + b_uv   (o2 folded; emb never materialized)
    mma_gemm<<<gUV, blk, DYN_BYTES>>>(p_h0, DD, wt_uv, p_buv, p_uv, 2 * DD, NN, DD, 0);
    // per-graph: yp = leaky(y@py + py_b); w = yp@W3 + pc1_b
    mma_gemm<<<gG, blk, DYN_BYTES>>>(p_yh, DD, wt_py, py_b, p_yp, DD, GG, DD, 2);
    mma_gemm<<<gG, blk, DYN_BYTES>>>(p_yp, DD, wt_W3, pc1_b, p_w, DD, GG, DD, 0);
    // fused edge head: relu(u+v+w) @ pc2 -> sigmoid -> out; std copy
    edge_head<<<(EE + 7) / 8, 256>>>(p_uv, p_w, edge_index, batch,
                                     pc2_W, pc2_b, edge_label, out, EE);

    (void)n_in; (void)in_sizes; (void)out_size;
}

// round 12
// speedup vs baseline: 1.1960x; 1.0631x over previous
#include <cuda_runtime.h>
#include <cuda_fp16.h>
#include <cstdint>
#include <math.h>

// Problem shapes (fixed by setup_inputs)
#define NN 40000
#define EE 100000
#define DD 768
#define GG 128
#define D3 2304
#define SS 589824                     // 768*768 elements

// ---------------- scratch (static device globals; allocation-free) ----------
__device__ static __half g_xh [(size_t)NN * DD];        // x in fp16
__device__ static __half g_h0 [(size_t)NN * DD];        // h0 / t
__device__ static __half g_emb3[(size_t)NN * D3];       // concat(h1,h2,h3)
__device__ static __half g_uv [(size_t)NN * 2 * DD];    // [u | v] per node
__device__ static __half g_yh [(size_t)GG * DD];        // y in fp16
__device__ static __half g_yp [(size_t)GG * DD];        // leaky(y@py+b)
__device__ static __half g_w  [(size_t)GG * DD];        // yp@W3 + pc1_b per graph
__device__ static __half g_wT [8257536];                // weights: 14 * 768*768 halves
__device__ static float  g_buv[2 * DD];                 // bias for uv GEMM
__device__ static float  g_zero[2 * DD];                // zero bias (zero-init)

// ---------------- helpers ----------------------------------------------------
__device__ __forceinline__ uint32_t smem_u32(const void* p) {
    uint32_t a;
    asm("{ .reg .u64 t; cvta.to.shared.u64 t, %1; cvt.u32.u64 %0, t; }" : "=r"(a) : "l"(p));
    return a;
}

__device__ __forceinline__ void cp_async16(uint32_t dst, const void* src, bool pred) {
    int sz = pred ? 16 : 0;
    asm volatile("cp.async.cg.shared.global [%0], [%1], 16, %2;"
                 :: "r"(dst), "l"(src), "r"(sz) : "memory");
}
#define CP_COMMIT() asm volatile("cp.async.commit_group;" ::: "memory")
#define CP_WAIT(n)  asm volatile("cp.async.wait_group %0;" :: "n"(n) : "memory")

__device__ __forceinline__ void ldsm_x4(uint32_t& r0, uint32_t& r1, uint32_t& r2, uint32_t& r3,
                                        uint32_t addr) {
    asm volatile("ldmatrix.sync.aligned.m8n8.x4.shared.b16 {%0,%1,%2,%3}, [%4];"
                 : "=r"(r0), "=r"(r1), "=r"(r2), "=r"(r3) : "r"(addr));
}

__device__ __forceinline__ void mma_f16(float d[4], const uint32_t a[4], const uint32_t b[2]) {
    asm volatile(
        "mma.sync.aligned.m16n8k16.row.col.f32.f16.f16.f32 "
        "{%0,%1,%2,%3}, {%4,%5,%6,%7}, {%8,%9}, {%0,%1,%2,%3};"
        : "+f"(d[0]), "+f"(d[1]), "+f"(d[2]), "+f"(d[3])
        : "r"(a[0]), "r"(a[1]), "r"(a[2]), "r"(a[3]), "r"(b[0]), "r"(b[1]));
}

#define SW(o) ((o) ^ (((o) >> 3) & 0x70))   // SW128 byte swizzle within 1KB atom

// ---------------- fp16 mma.sync GEMM (R5/R8 proven config, NO minBlocks) ------
// C[M,N] = act(A[M,K] @ Bt[N,K]^T + bias),  A/Bt/C fp16, bias fp32, accum fp32.
// BM=128, BN=128, BK=64 halves (128B rows, SW128). 8 warps: 4M x 2N (32x64 tile).
#define BM 128
#define BN 128
#define BK 64
#define TILE_BYTES 16384                   // 128 rows * 128B
#define STAGE_BYTES (2 * TILE_BYTES)       // A then B: 32 KB
#define NSTAGE 3
#define DYN_BYTES (NSTAGE * STAGE_BYTES)   // 96 KB -> 2 CTAs/SM

__global__ __launch_bounds__(256) void mma_gemm(
    const __half* __restrict__ A, int lda,
    const __half* __restrict__ Bt,
    const float* __restrict__ bias,
    __half* __restrict__ C, int ldc,
    int M, int K, int act)
{
    extern __shared__ char sh[];

    const int tid = threadIdx.x;
    const int wid = tid >> 5, lane = tid & 31;
    const int g = lane >> 2, t = lane & 3;
    const int wm = wid & 3, wn = wid >> 2;      // 4 M-warps x 2 N-warps
    const int m0 = blockIdx.y * BM;
    const int n0 = blockIdx.x * BN;

    const int nk = K / BK;
    const uint32_t shbase = smem_u32(sh);

    const int lrow0 = tid >> 3;           // +32*i
    const int lchB  = (tid & 7) * 16;
    const int lchH  = (tid & 7) * 8;

    auto issue_tile = [&](int kt) {
        if (kt < nk) {
            uint32_t As = shbase + (uint32_t)(kt % NSTAGE) * STAGE_BYTES;
            uint32_t Bs = As + TILE_BYTES;
            #pragma unroll
            for (int i = 0; i < 4; i++) {
                int row = lrow0 + i * 32;
                int gr = m0 + row;
                cp_async16(As + SW((uint32_t)(row * 128 + lchB)),
                           A + (long long)gr * lda + kt * BK + lchH, gr < M);
                cp_async16(Bs + SW((uint32_t)(row * 128 + lchB)),
                           Bt + (long long)(n0 + row) * K + kt * BK + lchH, true);
            }
        }
        CP_COMMIT();
    };

    float acc[2][8][4];
    #pragma unroll
    for (int i = 0; i < 2; i++)
        #pragma unroll
        for (int j = 0; j < 8; j++)
            #pragma unroll
            for (int q = 0; q < 4; q++) acc[i][j][q] = 0.f;

    issue_tile(0);
    issue_tile(1);

    const int lmRow = lane & 15;
    const int lmHi  = (lane & 16) ? 16 : 0;

    #pragma unroll 1
    for (int kt = 0; kt < nk; ++kt) {
        CP_WAIT(1);
        __syncthreads();
        issue_tile(kt + 2);

        uint32_t As = shbase + (uint32_t)(kt % NSTAGE) * STAGE_BYTES;
        uint32_t Bs = As + TILE_BYTES;

        #pragma unroll
        for (int ks = 0; ks < 4; ++ks) {
            const int kb = ks * 32 + lmHi;
            uint32_t a[2][4], b[8][2];
            #pragma unroll
            for (int mt = 0; mt < 2; ++mt) {
                int row = wm * 32 + mt * 16 + lmRow;
                ldsm_x4(a[mt][0], a[mt][1], a[mt][2], a[mt][3],
                        As + SW((uint32_t)(row * 128 + kb)));
            }
            #pragma unroll
            for (int nq = 0; nq < 4; ++nq) {
                int row = wn * 64 + nq * 16 + lmRow;
                ldsm_x4(b[2*nq][0], b[2*nq+1][0], b[2*nq][1], b[2*nq+1][1],
                        Bs + SW((uint32_t)(row * 128 + kb)));
            }
            #pragma unroll
            for (int mt = 0; mt < 2; ++mt)
                #pragma unroll
                for (int nt = 0; nt < 8; ++nt)
                    mma_f16(acc[mt][nt], a[mt], b[nt]);
        }
    }

    // ---- epilogue: bias + activation + fp16 store ----
    #pragma unroll
    for (int mt = 0; mt < 2; ++mt) {
        int row0 = m0 + wm * 32 + mt * 16 + g;
        #pragma unroll
        for (int nt = 0; nt < 8; ++nt) {
            int col = n0 + wn * 64 + nt * 8 + t * 2;
            float2 bb = *(const float2*)(bias + col);
            float v0 = acc[mt][nt][0] + bb.x;
            float v1 = acc[mt][nt][1] + bb.y;
            float v2 = acc[mt][nt][2] + bb.x;
            float v3 = acc[mt][nt][3] + bb.y;
            if (act == 1) {
                v0 = fmaxf(v0, 0.f); v1 = fmaxf(v1, 0.f);
                v2 = fmaxf(v2, 0.f); v3 = fmaxf(v3, 0.f);
            } else if (act == 2) {
                v0 = (v0 > 0.f) ? v0 : 0.4f * v0;  v1 = (v1 > 0.f) ? v1 : 0.4f * v1;
                v2 = (v2 > 0.f) ? v2 : 0.4f * v2;  v3 = (v3 > 0.f) ? v3 : 0.4f * v3;
            }
            if (row0 < M)
                *(__half2*)(C + (long long)row0 * ldc + col) =
                    __float22half2_rn(make_float2(v0, v1));
            if (row0 + 8 < M)
                *(__half2*)(C + (long long)(row0 + 8) * ldc + col) =
                    __float22half2_rn(make_float2(v2, v3));
        }
    }
}

// ---------------- fused prep: converts + transposes (no bias_uv tail) ---------
// Range decode (1-D grid):
//  [0, 30672)            convert x|y|o2W fp32->fp16 (float4 granularity)
//  [30672, 35280)        8x 768x768 transpose (576 blocks each)
//  [35280, 37008)        o1 transpose (24 n x 72 k)
#define PF_CVT  30672
#define PF_T8   4608
#define PF_TO1  1728
#define PF_TOTAL (PF_CVT + PF_T8 + PF_TO1)

struct PrepPack {
    const float* x; const float* y; const float* o2W;
    const float* w8[8];                  // ah,c0,c1,c2,py,W1,W2,W3
    const float* o1W;
};

__global__ __launch_bounds__(256) void prep_fused(PrepPack P)
{
    __shared__ float tb[32][33];
    const int bid = blockIdx.x;
    const int tid = threadIdx.x;

    if (bid < PF_CVT) {
        // flat convert of [x | y | o2W]
        const long long nx = (long long)NN * DD;
        const long long ny = (long long)GG * DD;
        const long long nw = (long long)DD * DD;
        long long i = ((long long)bid * 256 + tid) * 4;
        const float* src; __half* dst; long long j;
        if (i < nx) { src = P.x; dst = g_xh; j = i; }
        else if (i < nx + ny) { src = P.y; dst = g_yh; j = i - nx; }
        else if (i < nx + ny + nw) { src = P.o2W; dst = g_wT + 13 * (size_t)SS; j = i - nx - ny; }
        else return;
        float4 v = *(const float4*)(src + j);
        *(__half2*)(dst + j)     = __float22half2_rn(make_float2(v.x, v.y));
        *(__half2*)(dst + j + 2) = __float22half2_rn(make_float2(v.z, v.w));
    } else if (bid < PF_CVT + PF_T8) {
        int idx = bid - PF_CVT;
        int z = idx / 576, rem = idx % 576;
        const float* W = P.w8[z];
        __half* Wt = g_wT + (size_t)z * SS;
        int n0 = (rem % 24) * 32, k0 = (rem / 24) * 32;
        int xq = tid & 31, yq = tid >> 5;
        #pragma unroll
        for (int i = 0; i < 32; i += 8)
            tb[yq + i][xq] = W[(long long)(k0 + yq + i) * DD + n0 + xq];
        __syncthreads();
        #pragma unroll
        for (int i = 0; i < 32; i += 8)
            Wt[(long long)(n0 + yq + i) * DD + k0 + xq] = __float2half_rn(tb[xq][yq + i]);
    } else {
        int idx = bid - PF_CVT - PF_T8;
        __half* Wt = g_wT + 8 * (size_t)SS;
        int n0 = (idx % 24) * 32, k0 = (idx / 24) * 32;
        int xq = tid & 31, yq = tid >> 5;
        #pragma unroll
        for (int i = 0; i < 32; i += 8)
            tb[yq + i][xq] = P.o1W[(long long)(k0 + yq + i) * DD + n0 + xq];
        __syncthreads();
        #pragma unroll
        for (int i = 0; i < 32; i += 8)
            Wt[(long long)(n0 + yq + i) * D3 + k0 + xq] = __float2half_rn(tb[xq][yq + i]);
    }
}

// b_uv[n] = sum_k o2_b[k] * W12[n,k]  — one warp per n (reads fp16 wt_W12 rows)
__global__ __launch_bounds__(256) void bias_uv(
    const __half* __restrict__ wt_W12, const float* __restrict__ o2_b,
    float* __restrict__ buv)
{
    int gw = (blockIdx.x * 256 + threadIdx.x) >> 5;   // warp id = output n
    int lane = threadIdx.x & 31;
    if (gw >= 2 * DD) return;
    const __half2* wrow = (const __half2*)(wt_W12 + (long long)gw * DD);
    float s = 0.f;
    #pragma unroll
    for (int i = lane; i < DD / 2; i += 32) {
        float2 f = __half22float2(wrow[i]);
        s = fmaf(f.x, o2_b[2 * i], s);
        s = fmaf(f.y, o2_b[2 * i + 1], s);
    }
    #pragma unroll
    for (int off = 16; off > 0; off >>= 1)
        s += __shfl_xor_sync(0xffffffffu, s, off);
    if (lane == 0) buv[gw] = s;
}

// ---------------- fused edge head ---------------------------------------------
// per edge: q = relu(u[src] + v[dst] + w[batch[src]]); pred = sigmoid(q@pc2 + b2)
__global__ __launch_bounds__(256) void edge_head(
    const __half* __restrict__ uv, const __half* __restrict__ w,
    const int* __restrict__ edge_index, const int* __restrict__ batch,
    const float* __restrict__ pc2W /*[768,2]*/, const float* __restrict__ b2,
    const float* __restrict__ lab, float* __restrict__ out, int E)
{
    __shared__ float w0[DD];
    __shared__ float w1[DD];
    for (int i = threadIdx.x; i < DD; i += blockDim.x) {
        w0[i] = pc2W[2 * i];
        w1[i] = pc2W[2 * i + 1];
    }
    __syncthreads();

    int warp = threadIdx.x >> 5;
    int lane = threadIdx.x & 31;
    int e = blockIdx.x * 8 + warp;
    if (e >= E) return;

    int src = edge_index[e];
    int dst = edge_index[E + e];
    int gph = batch[src];

    const __half2* ur = (const __half2*)(uv + (long long)src * (2 * DD));
    const __half2* vr = (const __half2*)(uv + (long long)dst * (2 * DD) + DD);
    const __half2* wr = (const __half2*)(w  + (long long)gph * DD);

    float a0 = 0.f, a1 = 0.f;
    #pragma unroll
    for (int i = 0; i < 12; i++) {
        int k = lane + i * 32;               // half2 index, 0..383
        float2 fu = __half22float2(ur[k]);
        float2 fv = __half22float2(vr[k]);
        float2 fw = __half22float2(wr[k]);
        float q0 = fmaxf(fu.x + fv.x + fw.x, 0.f);
        float q1 = fmaxf(fu.y + fv.y + fw.y, 0.f);
        a0 = fmaf(q0, w0[2*k], a0);   a0 = fmaf(q1, w0[2*k+1], a0);
        a1 = fmaf(q0, w1[2*k], a1);   a1 = fmaf(q1, w1[2*k+1], a1);
    }
    #pragma unroll
    for (int off = 16; off > 0; off >>= 1) {
        a0 += __shfl_xor_sync(0xffffffffu, a0, off);
        a1 += __shfl_xor_sync(0xffffffffu, a1, off);
    }
    if (lane == 0) {
        out[2 * e]     = 1.f / (1.f + expf(-(a0 + b2[0])));
        out[2 * e + 1] = 1.f / (1.f + expf(-(a1 + b2[1])));
        out[2 * E + e] = lab[e];
    }
}

// ---------------- host launch ------------------------------------------------
static __half *p_xh = nullptr, *p_h0 = nullptr, *p_emb3 = nullptr, *p_uv = nullptr,
              *p_yh = nullptr, *p_yp = nullptr, *p_w = nullptr, *p_wT = nullptr;
static float  *p_buv = nullptr, *p_zero = nullptr;

extern "C" void kernel_launch(void* const* d_in, const int* in_sizes, int n_in,
                              void* d_out, int out_size)
{
    if (!p_wT) {  // one-time setup on the (uncaptured) correctness call
        cudaGetSymbolAddress((void**)&p_xh,   g_xh);
        cudaGetSymbolAddress((void**)&p_h0,   g_h0);
        cudaGetSymbolAddress((void**)&p_emb3, g_emb3);
        cudaGetSymbolAddress((void**)&p_uv,   g_uv);
        cudaGetSymbolAddress((void**)&p_yh,   g_yh);
        cudaGetSymbolAddress((void**)&p_yp,   g_yp);
        cudaGetSymbolAddress((void**)&p_w,    g_w);
        cudaGetSymbolAddress((void**)&p_wT,   g_wT);
        cudaGetSymbolAddress((void**)&p_buv,  g_buv);
        cudaGetSymbolAddress((void**)&p_zero, g_zero);
        cudaFuncSetAttribute(mma_gemm,
                             cudaFuncAttributeMaxDynamicSharedMemorySize, DYN_BYTES);
    }

    const float* x          = (const float*)d_in[0];
    const int*   edge_index = (const int*  )d_in[1];
    const int*   batch      = (const int*  )d_in[2];
    const float* y          = (const float*)d_in[5];
    const float* edge_label = (const float*)d_in[6];
    const float* ah_W  = (const float*)d_in[7];
    const float* ah_b  = (const float*)d_in[8];
    const float* c0_W  = (const float*)d_in[9];
    const float* c0_b  = (const float*)d_in[10];
    const float* c1_W  = (const float*)d_in[11];
    const float* c1_b  = (const float*)d_in[12];
    const float* c2_W  = (const float*)d_in[13];
    const float* c2_b  = (const float*)d_in[14];
    const float* o1_W  = (const float*)d_in[15];
    const float* o1_b  = (const float*)d_in[16];
    const float* o2_W  = (const float*)d_in[17];
    const float* o2_b  = (const float*)d_in[18];
    const float* py_W  = (const float*)d_in[19];
    const float* py_b  = (const float*)d_in[20];
    const float* pc1_W = (const float*)d_in[21];
    const float* pc1_b = (const float*)d_in[22];
    const float* pc2_W = (const float*)d_in[23];
    const float* pc2_b = (const float*)d_in[24];

    float* out = (float*)d_out;

    // weight slots in g_wT (halves):
    // 0 ah | 1 c0 | 2 c1 | 3 c2 | 4 py | 5 W1 | 6 W2 | 7 W3 | 8..10 o1 | 11..12 uv | 13 o2h
    __half* wt_ah  = p_wT;
    __half* wt_c0  = p_wT + (size_t)SS;
    __half* wt_c1  = p_wT + 2 * (size_t)SS;
    __half* wt_c2  = p_wT + 3 * (size_t)SS;
    __half* wt_py  = p_wT + 4 * (size_t)SS;
    __half* wt_W12 = p_wT + 5 * (size_t)SS;     // W1|W2 contiguous (M=1536)
    __half* wt_W3  = p_wT + 7 * (size_t)SS;
    __half* wt_o1  = p_wT + 8 * (size_t)SS;     // [768, 2304]
    __half* wt_uv  = p_wT + 11 * (size_t)SS;    // composite [1536, 768]
    __half* o2h    = p_wT + 13 * (size_t)SS;    // o2_W fp16 row-major

    // ---- prep: fused converts/transposes, then warp-parallel bias_uv ----
    PrepPack P;
    P.x = x; P.y = y; P.o2W = o2_W;
    P.w8[0] = ah_W; P.w8[1] = c0_W; P.w8[2] = c1_W; P.w8[3] = c2_W;
    P.w8[4] = py_W;
    P.w8[5] = pc1_W;                  // W1
    P.w8[6] = pc1_W + 768 * DD;       // W2
    P.w8[7] = pc1_W + 1536 * DD;      // W3
    P.o1W = o1_W;
    prep_fused<<<PF_TOTAL, 256>>>(P);
    bias_uv<<<(2 * DD * 32 + 255) / 256, 256>>>(wt_W12, o2_b, p_buv);

    // composite weights: rows 0..767 from W1, 768..1535 from W2
    {
        dim3 gC(DD / BN, 2 * DD / BM);    // 6 x 12
        mma_gemm<<<gC, 256, DYN_BYTES>>>(wt_W12, DD, o2h, p_zero, wt_uv, DD, 2 * DD, DD, 0);
    }

    dim3 blk(256);
    dim3 gN(DD / BN, (NN + BM - 1) / BM);        // 6 x 313
    dim3 gUV(2 * DD / BN, (NN + BM - 1) / BM);   // 12 x 313
    dim3 gG(DD / BN, 1);

    // Encoder
    mma_gemm<<<gN, blk, DYN_BYTES>>>(p_xh, DD, wt_ah, ah_b, p_h0, DD, NN, DD, 1);
    mma_gemm<<<gN, blk, DYN_BYTES>>>(p_h0, DD, wt_c0, c0_b, p_emb3, D3, NN, DD, 1);
    mma_gemm<<<gN, blk, DYN_BYTES>>>(p_emb3, D3, wt_c1, c1_b, p_emb3 + DD, D3, NN, DD, 1);
    mma_gemm<<<gN, blk, DYN_BYTES>>>(p_emb3 + DD, D3, wt_c2, c2_b, p_emb3 + 2 * DD, D3, NN, DD, 1);
    mma_gemm<<<gN, blk, DYN_BYTES>>>(p_emb3, D3, wt_o1, o1_b, p_h0, DD, NN, D3, 1);
    // uv = t @ [o2W*W1 | o2W*W2] + b_uv   (o2 folded; emb never materialized)
    mma_gemm<<<gUV, blk, DYN_BYTES>>>(p_h0, DD, wt_uv, p_buv, p_uv, 2 * DD, NN, DD, 0);
    // per-graph: yp = leaky(y@py + py_b); w = yp@W3 + pc1_b
    mma_gemm<<<gG, blk, DYN_BYTES>>>(p_yh, DD, wt_py, py_b, p_yp, DD, GG, DD, 2);
    mma_gemm<<<gG, blk, DYN_BYTES>>>(p_yp, DD, wt_W3, pc1_b, p_w, DD, GG, DD, 0);
    // fused edge head: relu(u+v+w) @ pc2 -> sigmoid -> out; std copy
    edge_head<<<(EE + 7) / 8, 256>>>(p_uv, p_w, edge_index, batch,
                                     pc2_W, pc2_b, edge_label, out, EE);

    (void)n_in; (void)in_sizes; (void)out_size;
}

// round 13
// speedup vs baseline: 1.2517x; 1.0465x over previous
#include <cuda_runtime.h>
#include <cuda_fp16.h>
#include <cstdint>
#include <math.h>

// Problem shapes (fixed by setup_inputs)
#define NN 40000
#define EE 100000
#define DD 768
#define GG 128
#define D3 2304

// ---------------- scratch (static device globals; allocation-free) ----------
__device__ static __half g_xh [(size_t)NN * DD];        // x in fp16
__device__ static __half g_h0 [(size_t)NN * DD];        // h0 / t
__device__ static __half g_emb3[(size_t)NN * D3];       // concat(h1,h2,h3)
__device__ static __half g_uv [(size_t)NN * 2 * DD];    // [u | v] per node
__device__ static __half g_yh [(size_t)GG * DD];        // y in fp16
__device__ static __half g_yp [(size_t)GG * DD];        // leaky(y@py+b)
__device__ static __half g_w  [(size_t)GG * DD];        // yp@W3 + pc1_b per graph
__device__ static __half g_wT [8257536];                // weights: 14 * 768*768 halves
__device__ static float  g_buv[2 * DD];                 // bias for uv GEMM
__device__ static float  g_zero[2 * DD];                // zero bias (device globals zero-init)

// ---------------- helpers ----------------------------------------------------
__device__ __forceinline__ uint32_t smem_u32(const void* p) {
    uint32_t a;
    asm("{ .reg .u64 t; cvta.to.shared.u64 t, %1; cvt.u32.u64 %0, t; }" : "=r"(a) : "l"(p));
    return a;
}

__device__ __forceinline__ void cp_async16(uint32_t dst, const void* src, bool pred) {
    int sz = pred ? 16 : 0;
    asm volatile("cp.async.cg.shared.global [%0], [%1], 16, %2;"
                 :: "r"(dst), "l"(src), "r"(sz) : "memory");
}
#define CP_COMMIT() asm volatile("cp.async.commit_group;" ::: "memory")
#define CP_WAIT(n)  asm volatile("cp.async.wait_group %0;" :: "n"(n) : "memory")

__device__ __forceinline__ void ldsm_x4(uint32_t& r0, uint32_t& r1, uint32_t& r2, uint32_t& r3,
                                        uint32_t addr) {
    asm volatile("ldmatrix.sync.aligned.m8n8.x4.shared.b16 {%0,%1,%2,%3}, [%4];"
                 : "=r"(r0), "=r"(r1), "=r"(r2), "=r"(r3) : "r"(addr));
}

__device__ __forceinline__ void mma_f16(float d[4], const uint32_t a[4], const uint32_t b[2]) {
    asm volatile(
        "mma.sync.aligned.m16n8k16.row.col.f32.f16.f16.f32 "
        "{%0,%1,%2,%3}, {%4,%5,%6,%7}, {%8,%9}, {%0,%1,%2,%3};"
        : "+f"(d[0]), "+f"(d[1]), "+f"(d[2]), "+f"(d[3])
        : "r"(a[0]), "r"(a[1]), "r"(a[2]), "r"(a[3]), "r"(b[0]), "r"(b[1]));
}

#define SW(o) ((o) ^ (((o) >> 3) & 0x70))   // SW128 byte swizzle within 1KB atom

// ---------------- fp16 mma.sync GEMM (R5/R8 proven config) --------------------
// C[M,N] = act(A[M,K] @ Bt[N,K]^T + bias),  A/Bt/C fp16, bias fp32, accum fp32.
// BM=128, BN=128, BK=64 halves (128B rows, SW128). 8 warps: 4M x 2N (32x64 tile).
#define BM 128
#define BN 128
#define BK 64
#define TILE_BYTES 16384                   // 128 rows * 128B
#define STAGE_BYTES (2 * TILE_BYTES)       // A then B: 32 KB
#define NSTAGE 3
#define DYN_BYTES (NSTAGE * STAGE_BYTES)   // 96 KB -> 2 CTAs/SM

__global__ __launch_bounds__(256) void mma_gemm(
    const __half* __restrict__ A, int lda,
    const __half* __restrict__ Bt,
    const float* __restrict__ bias,
    __half* __restrict__ C, int ldc,
    int M, int K, int act)
{
    extern __shared__ char sh[];

    const int tid = threadIdx.x;
    const int wid = tid >> 5, lane = tid & 31;
    const int g = lane >> 2, t = lane & 3;
    const int wm = wid & 3, wn = wid >> 2;      // 4 M-warps x 2 N-warps
    const int m0 = blockIdx.y * BM;
    const int n0 = blockIdx.x * BN;

    const int nk = K / BK;
    const uint32_t shbase = smem_u32(sh);

    const int lrow0 = tid >> 3;           // +32*i
    const int lchB  = (tid & 7) * 16;
    const int lchH  = (tid & 7) * 8;

    auto issue_tile = [&](int kt) {
        if (kt < nk) {
            uint32_t As = shbase + (uint32_t)(kt % NSTAGE) * STAGE_BYTES;
            uint32_t Bs = As + TILE_BYTES;
            #pragma unroll
            for (int i = 0; i < 4; i++) {
                int row = lrow0 + i * 32;
                int gr = m0 + row;
                cp_async16(As + SW((uint32_t)(row * 128 + lchB)),
                           A + (long long)gr * lda + kt * BK + lchH, gr < M);
                cp_async16(Bs + SW((uint32_t)(row * 128 + lchB)),
                           Bt + (long long)(n0 + row) * K + kt * BK + lchH, true);
            }
        }
        CP_COMMIT();
    };

    float acc[2][8][4];
    #pragma unroll
    for (int i = 0; i < 2; i++)
        #pragma unroll
        for (int j = 0; j < 8; j++)
            #pragma unroll
            for (int q = 0; q < 4; q++) acc[i][j][q] = 0.f;

    issue_tile(0);
    issue_tile(1);

    const int lmRow = lane & 15;
    const int lmHi  = (lane & 16) ? 16 : 0;

    #pragma unroll 1
    for (int kt = 0; kt < nk; ++kt) {
        CP_WAIT(1);
        __syncthreads();
        issue_tile(kt + 2);

        uint32_t As = shbase + (uint32_t)(kt % NSTAGE) * STAGE_BYTES;
        uint32_t Bs = As + TILE_BYTES;

        #pragma unroll
        for (int ks = 0; ks < 4; ++ks) {
            const int kb = ks * 32 + lmHi;
            uint32_t a[2][4], b[8][2];
            #pragma unroll
            for (int mt = 0; mt < 2; ++mt) {
                int row = wm * 32 + mt * 16 + lmRow;
                ldsm_x4(a[mt][0], a[mt][1], a[mt][2], a[mt][3],
                        As + SW((uint32_t)(row * 128 + kb)));
            }
            #pragma unroll
            for (int nq = 0; nq < 4; ++nq) {
                int row = wn * 64 + nq * 16 + lmRow;
                ldsm_x4(b[2*nq][0], b[2*nq+1][0], b[2*nq][1], b[2*nq+1][1],
                        Bs + SW((uint32_t)(row * 128 + kb)));
            }
            #pragma unroll
            for (int mt = 0; mt < 2; ++mt)
                #pragma unroll
                for (int nt = 0; nt < 8; ++nt)
                    mma_f16(acc[mt][nt], a[mt], b[nt]);
        }
    }

    // ---- epilogue: bias + activation + fp16 store ----
    #pragma unroll
    for (int mt = 0; mt < 2; ++mt) {
        int row0 = m0 + wm * 32 + mt * 16 + g;
        #pragma unroll
        for (int nt = 0; nt < 8; ++nt) {
            int col = n0 + wn * 64 + nt * 8 + t * 2;
            float2 bb = *(const float2*)(bias + col);
            float v0 = acc[mt][nt][0] + bb.x;
            float v1 = acc[mt][nt][1] + bb.y;
            float v2 = acc[mt][nt][2] + bb.x;
            float v3 = acc[mt][nt][3] + bb.y;
            if (act == 1) {
                v0 = fmaxf(v0, 0.f); v1 = fmaxf(v1, 0.f);
                v2 = fmaxf(v2, 0.f); v3 = fmaxf(v3, 0.f);
            } else if (act == 2) {
                v0 = (v0 > 0.f) ? v0 : 0.4f * v0;  v1 = (v1 > 0.f) ? v1 : 0.4f * v1;
                v2 = (v2 > 0.f) ? v2 : 0.4f * v2;  v3 = (v3 > 0.f) ? v3 : 0.4f * v3;
            }
            if (row0 < M)
                *(__half2*)(C + (long long)row0 * ldc + col) =
                    __float22half2_rn(make_float2(v0, v1));
            if (row0 + 8 < M)
                *(__half2*)(C + (long long)(row0 + 8) * ldc + col) =
                    __float22half2_rn(make_float2(v2, v3));
        }
    }
}

// ---------------- batched prep kernels ----------------------------------------
struct Ptr8 { const float* p[8]; };

// 8x 768x768 transposes: Wt[n*768 + k] = W[k*768 + n], fp16 out
__global__ __launch_bounds__(256) void transpose8(Ptr8 src, __half* dstBase)
{
    const float* W = src.p[blockIdx.z];
    __half* Wt = dstBase + (size_t)blockIdx.z * ((size_t)DD * DD);
    __shared__ float tb[32][33];
    int n0 = blockIdx.x * 32, k0 = blockIdx.y * 32;
    int x = threadIdx.x & 31, y = threadIdx.x >> 5;
    #pragma unroll
    for (int i = 0; i < 32; i += 8)
        tb[y + i][x] = W[(long long)(k0 + y + i) * DD + n0 + x];
    __syncthreads();
    #pragma unroll
    for (int i = 0; i < 32; i += 8)
        Wt[(long long)(n0 + y + i) * DD + k0 + x] = __float2half_rn(tb[x][y + i]);
}

// o1 transpose: [2304(K) x 768(N)] -> Wt[n*2304 + k]
__global__ __launch_bounds__(256) void transpose_o1(
    const float* __restrict__ W, __half* __restrict__ Wt)
{
    __shared__ float tb[32][33];
    int n0 = blockIdx.x * 32, k0 = blockIdx.y * 32;
    int x = threadIdx.x & 31, y = threadIdx.x >> 5;
    #pragma unroll
    for (int i = 0; i < 32; i += 8)
        tb[y + i][x] = W[(long long)(k0 + y + i) * DD + n0 + x];
    __syncthreads();
    #pragma unroll
    for (int i = 0; i < 32; i += 8)
        Wt[(long long)(n0 + y + i) * D3 + k0 + x] = __float2half_rn(tb[x][y + i]);
}

// fp32->fp16 flat convert of x, y, o2_W into xh, yh, o2h
__global__ __launch_bounds__(256) void convert_all(
    const float* __restrict__ x, const float* __restrict__ y,
    const float* __restrict__ o2W,
    __half* __restrict__ xh, __half* __restrict__ yh, __half* __restrict__ o2h)
{
    const long long nx = (long long)NN * DD;
    const long long ny = (long long)GG * DD;
    const long long nw = (long long)DD * DD;
    long long i = ((long long)blockIdx.x * 256 + threadIdx.x) * 4;
    const float* src; __half* dst; long long j;
    if (i < nx) { src = x; dst = xh; j = i; }
    else if (i < nx + ny) { src = y; dst = yh; j = i - nx; }
    else if (i < nx + ny + nw) { src = o2W; dst = o2h; j = i - nx - ny; }
    else return;
    float4 v = *(const float4*)(src + j);
    *(__half2*)(dst + j)     = __float22half2_rn(make_float2(v.x, v.y));
    *(__half2*)(dst + j + 2) = __float22half2_rn(make_float2(v.z, v.w));
}

// b_uv[n] = sum_k o2_b[k] * W12[n,k]  — one warp per n (wt_W1|wt_W2 contiguous)
__global__ __launch_bounds__(256) void bias_uv(
    const __half* __restrict__ wt_W12, const float* __restrict__ o2_b,
    float* __restrict__ buv)
{
    int gw = (blockIdx.x * 256 + threadIdx.x) >> 5;   // warp id = output n
    int lane = threadIdx.x & 31;
    if (gw >= 2 * DD) return;
    const __half2* wrow = (const __half2*)(wt_W12 + (long long)gw * DD);
    float s = 0.f;
    #pragma unroll
    for (int i = lane; i < DD / 2; i += 32) {
        float2 f = __half22float2(wrow[i]);
        s = fmaf(f.x, o2_b[2 * i], s);
        s = fmaf(f.y, o2_b[2 * i + 1], s);
    }
    #pragma unroll
    for (int off = 16; off > 0; off >>= 1)
        s += __shfl_xor_sync(0xffffffffu, s, off);
    if (lane == 0) buv[gw] = s;
}

// ---------------- fused edge head ---------------------------------------------
// per edge: q = relu(u[src] + v[dst] + w[batch[src]]); pred = sigmoid(q@pc2 + b2)
__global__ __launch_bounds__(256) void edge_head(
    const __half* __restrict__ uv, const __half* __restrict__ w,
    const int* __restrict__ edge_index, const int* __restrict__ batch,
    const float* __restrict__ pc2W /*[768,2]*/, const float* __restrict__ b2,
    const float* __restrict__ lab, float* __restrict__ out, int E)
{
    __shared__ float w0[DD];
    __shared__ float w1[DD];
    for (int i = threadIdx.x; i < DD; i += blockDim.x) {
        w0[i] = pc2W[2 * i];
        w1[i] = pc2W[2 * i + 1];
    }
    __syncthreads();

    int warp = threadIdx.x >> 5;
    int lane = threadIdx.x & 31;
    int e = blockIdx.x * 8 + warp;
    if (e >= E) return;

    int src = edge_index[e];
    int dst = edge_index[E + e];
    int gph = batch[src];

    const __half2* ur = (const __half2*)(uv + (long long)src * (2 * DD));
    const __half2* vr = (const __half2*)(uv + (long long)dst * (2 * DD) + DD);
    const __half2* wr = (const __half2*)(w  + (long long)gph * DD);

    float a0 = 0.f, a1 = 0.f;
    #pragma unroll
    for (int i = 0; i < 12; i++) {
        int k = lane + i * 32;               // half2 index, 0..383
        float2 fu = __half22float2(ur[k]);
        float2 fv = __half22float2(vr[k]);
        float2 fw = __half22float2(wr[k]);
        float q0 = fmaxf(fu.x + fv.x + fw.x, 0.f);
        float q1 = fmaxf(fu.y + fv.y + fw.y, 0.f);
        a0 = fmaf(q0, w0[2*k], a0);   a0 = fmaf(q1, w0[2*k+1], a0);
        a1 = fmaf(q0, w1[2*k], a1);   a1 = fmaf(q1, w1[2*k+1], a1);
    }
    #pragma unroll
    for (int off = 16; off > 0; off >>= 1) {
        a0 += __shfl_xor_sync(0xffffffffu, a0, off);
        a1 += __shfl_xor_sync(0xffffffffu, a1, off);
    }
    if (lane == 0) {
        out[2 * e]     = 1.f / (1.f + expf(-(a0 + b2[0])));
        out[2 * e + 1] = 1.f / (1.f + expf(-(a1 + b2[1])));
        out[2 * E + e] = lab[e];
    }
}

// ---------------- host launch ------------------------------------------------
static __half *p_xh = nullptr, *p_h0 = nullptr, *p_emb3 = nullptr, *p_uv = nullptr,
              *p_yh = nullptr, *p_yp = nullptr, *p_w = nullptr, *p_wT = nullptr;
static float  *p_buv = nullptr, *p_zero = nullptr;

extern "C" void kernel_launch(void* const* d_in, const int* in_sizes, int n_in,
                              void* d_out, int out_size)
{
    if (!p_wT) {  // one-time setup on the (uncaptured) correctness call
        cudaGetSymbolAddress((void**)&p_xh,   g_xh);
        cudaGetSymbolAddress((void**)&p_h0,   g_h0);
        cudaGetSymbolAddress((void**)&p_emb3, g_emb3);
        cudaGetSymbolAddress((void**)&p_uv,   g_uv);
        cudaGetSymbolAddress((void**)&p_yh,   g_yh);
        cudaGetSymbolAddress((void**)&p_yp,   g_yp);
        cudaGetSymbolAddress((void**)&p_w,    g_w);
        cudaGetSymbolAddress((void**)&p_wT,   g_wT);
        cudaGetSymbolAddress((void**)&p_buv,  g_buv);
        cudaGetSymbolAddress((void**)&p_zero, g_zero);
        cudaFuncSetAttribute(mma_gemm,
                             cudaFuncAttributeMaxDynamicSharedMemorySize, DYN_BYTES);
    }

    const float* x          = (const float*)d_in[0];
    const int*   edge_index = (const int*  )d_in[1];
    const int*   batch      = (const int*  )d_in[2];
    const float* y          = (const float*)d_in[5];
    const float* edge_label = (const float*)d_in[6];
    const float* ah_W  = (const float*)d_in[7];
    const float* ah_b  = (const float*)d_in[8];
    const float* c0_W  = (const float*)d_in[9];
    const float* c0_b  = (const float*)d_in[10];
    const float* c1_W  = (const float*)d_in[11];
    const float* c1_b  = (const float*)d_in[12];
    const float* c2_W  = (const float*)d_in[13];
    const float* c2_b  = (const float*)d_in[14];
    const float* o1_W  = (const float*)d_in[15];
    const float* o1_b  = (const float*)d_in[16];
    const float* o2_W  = (const float*)d_in[17];
    const float* o2_b  = (const float*)d_in[18];
    const float* py_W  = (const float*)d_in[19];
    const float* py_b  = (const float*)d_in[20];
    const float* pc1_W = (const float*)d_in[21];
    const float* pc1_b = (const float*)d_in[22];
    const float* pc2_W = (const float*)d_in[23];
    const float* pc2_b = (const float*)d_in[24];

    float* out = (float*)d_out;

    const long long S = (long long)DD * DD;        // 589824
    __half* wt_ah  = p_wT;
    __half* wt_c0  = p_wT + S;
    __half* wt_c1  = p_wT + 2 * S;
    __half* wt_c2  = p_wT + 3 * S;
    __half* wt_py  = p_wT + 4 * S;
    __half* wt_W12 = p_wT + 5 * S;                 // W1|W2 contiguous (M=1536)
    __half* wt_W3  = p_wT + 7 * S;
    __half* wt_o1  = p_wT + 8 * S;                 // [768, 2304]
    __half* wt_uv  = p_wT + 11 * S;                // composite [1536, 768]
    __half* o2h    = p_wT + 13 * S;                // o2_W fp16 row-major

    // ---- prep ----
    {
        Ptr8 s8;
        s8.p[0] = ah_W; s8.p[1] = c0_W; s8.p[2] = c1_W; s8.p[3] = c2_W;
        s8.p[4] = py_W;
        s8.p[5] = pc1_W;                 // W1 = rows 0..767
        s8.p[6] = pc1_W + 768 * DD;      // W2
        s8.p[7] = pc1_W + 1536 * DD;     // W3
        transpose8<<<dim3(DD/32, DD/32, 8), 256>>>(s8, p_wT);
        transpose_o1<<<dim3(DD/32, D3/32), 256>>>(o1_W, wt_o1);
        long long tot = ((long long)NN * DD + (long long)GG * DD + (long long)DD * DD) / 4;
        convert_all<<<(unsigned)((tot + 255) / 256), 256>>>(x, y, o2_W, p_xh, p_yh, o2h);
        bias_uv<<<(2 * DD * 32 + 255) / 256, 256>>>(wt_W12, o2_b, p_buv);
        // composite weights, single launch: rows 0..767 from W1, 768..1535 from W2
        dim3 gC(DD / BN, 2 * DD / BM);    // 6 x 12
        mma_gemm<<<gC, 256, DYN_BYTES>>>(wt_W12, DD, o2h, p_zero, wt_uv, DD, 2 * DD, DD, 0);
    }

    dim3 blk(256);
    dim3 gN(DD / BN, (NN + BM - 1) / BM);        // 6 x 313
    dim3 gUV(2 * DD / BN, (NN + BM - 1) / BM);   // 12 x 313
    dim3 gG(DD / BN, 1);

    // Encoder
    mma_gemm<<<gN, blk, DYN_BYTES>>>(p_xh, DD, wt_ah, ah_b, p_h0, DD, NN, DD, 1);
    mma_gemm<<<gN, blk, DYN_BYTES>>>(p_h0, DD, wt_c0, c0_b, p_emb3, D3, NN, DD, 1);
    mma_gemm<<<gN, blk, DYN_BYTES>>>(p_emb3, D3, wt_c1, c1_b, p_emb3 + DD, D3, NN, DD, 1);
    mma_gemm<<<gN, blk, DYN_BYTES>>>(p_emb3 + DD, D3, wt_c2, c2_b, p_emb3 + 2 * DD, D3, NN, DD, 1);
    mma_gemm<<<gN, blk, DYN_BYTES>>>(p_emb3, D3, wt_o1, o1_b, p_h0, DD, NN, D3, 1);
    // uv = t @ [o2W*W1 | o2W*W2] + b_uv   (o2 folded; emb never materialized)
    mma_gemm<<<gUV, blk, DYN_BYTES>>>(p_h0, DD, wt_uv, p_buv, p_uv, 2 * DD, NN, DD, 0);
    // per-graph: yp = leaky(y@py + py_b); w = yp@W3 + pc1_b
    mma_gemm<<<gG, blk, DYN_BYTES>>>(p_yh, DD, wt_py, py_b, p_yp, DD, GG, DD, 2);
    mma_gemm<<<gG, blk, DYN_BYTES>>>(p_yp, DD, wt_W3, pc1_b, p_w, DD, GG, DD, 0);
    // fused edge head: relu(u+v+w) @ pc2 -> sigmoid -> out; std copy
    edge_head<<<(EE + 7) / 8, 256>>>(p_uv, p_w, edge_index, batch,
                                     pc2_W, pc2_b, edge_label, out, EE);

    (void)n_in; (void)in_sizes; (void)out_size;
}

// round 14
// speedup vs baseline: 1.2533x; 1.0013x over previous
#include <cuda_runtime.h>
#include <cuda_fp16.h>
#include <cstdint>
#include <math.h>

// Problem shapes (fixed by setup_inputs)
#define NN 40000
#define EE 100000
#define DD 768
#define GG 128
#define D3 2304

// ---------------- scratch (static device globals; allocation-free) ----------
__device__ static __half g_xh [(size_t)NN * DD];        // x in fp16
__device__ static __half g_h0 [(size_t)NN * DD];        // h0 / t
__device__ static __half g_emb3[(size_t)NN * D3];       // concat(h1,h2,h3)
__device__ static __half g_uv [(size_t)NN * 2 * DD];    // [u | v] per node
__device__ static __half g_yh [(size_t)GG * DD];        // y in fp16
__device__ static __half g_yp [(size_t)GG * DD];        // leaky(y@py+b)
__device__ static __half g_w  [(size_t)GG * DD];        // yp@W3 + pc1_b per graph
__device__ static __half g_wT [8257536];                // weights: 14 * 768*768 halves
__device__ static float  g_buv[2 * DD];                 // bias for uv GEMM
__device__ static float  g_zero[2 * DD];                // zero bias (device globals zero-init)
__device__ static int    g_sync;                        // epoch counter (never reset)

// ---------------- helpers ----------------------------------------------------
__device__ __forceinline__ uint32_t smem_u32(const void* p) {
    uint32_t a;
    asm("{ .reg .u64 t; cvta.to.shared.u64 t, %1; cvt.u32.u64 %0, t; }" : "=r"(a) : "l"(p));
    return a;
}

__device__ __forceinline__ void cp_async16(uint32_t dst, const void* src, bool pred) {
    int sz = pred ? 16 : 0;
    asm volatile("cp.async.cg.shared.global [%0], [%1], 16, %2;"
                 :: "r"(dst), "l"(src), "r"(sz) : "memory");
}
#define CP_COMMIT() asm volatile("cp.async.commit_group;" ::: "memory")
#define CP_WAIT(n)  asm volatile("cp.async.wait_group %0;" :: "n"(n) : "memory")

__device__ __forceinline__ void ldsm_x4(uint32_t& r0, uint32_t& r1, uint32_t& r2, uint32_t& r3,
                                        uint32_t addr) {
    asm volatile("ldmatrix.sync.aligned.m8n8.x4.shared.b16 {%0,%1,%2,%3}, [%4];"
                 : "=r"(r0), "=r"(r1), "=r"(r2), "=r"(r3) : "r"(addr));
}

__device__ __forceinline__ void mma_f16(float d[4], const uint32_t a[4], const uint32_t b[2]) {
    asm volatile(
        "mma.sync.aligned.m16n8k16.row.col.f32.f16.f16.f32 "
        "{%0,%1,%2,%3}, {%4,%5,%6,%7}, {%8,%9}, {%0,%1,%2,%3};"
        : "+f"(d[0]), "+f"(d[1]), "+f"(d[2]), "+f"(d[3])
        : "r"(a[0]), "r"(a[1]), "r"(a[2]), "r"(a[3]), "r"(b[0]), "r"(b[1]));
}

__device__ __forceinline__ int ld_acquire(const int* p) {
    int v;
    asm volatile("ld.acquire.gpu.global.b32 %0, [%1];" : "=r"(v) : "l"(p) : "memory");
    return v;
}

#define SW(o) ((o) ^ (((o) >> 3) & 0x70))   // SW128 byte swizzle within 1KB atom

// ---------------- fp16 mma.sync GEMM (R5/R8 proven config) --------------------
// C[M,N] = act(A[M,K] @ Bt[N,K]^T + bias),  A/Bt/C fp16, bias fp32, accum fp32.
// BM=128, BN=128, BK=64 halves (128B rows, SW128). 8 warps: 4M x 2N (32x64 tile).
#define BM 128
#define BN 128
#define BK 64
#define TILE_BYTES 16384                   // 128 rows * 128B
#define STAGE_BYTES (2 * TILE_BYTES)       // A then B: 32 KB
#define NSTAGE 3
#define DYN_BYTES (NSTAGE * STAGE_BYTES)   // 96 KB -> 2 CTAs/SM

__global__ __launch_bounds__(256) void mma_gemm(
    const __half* __restrict__ A, int lda,
    const __half* __restrict__ Bt,
    const float* __restrict__ bias,
    __half* __restrict__ C, int ldc,
    int M, int K, int act)
{
    extern __shared__ char sh[];

    const int tid = threadIdx.x;
    const int wid = tid >> 5, lane = tid & 31;
    const int g = lane >> 2, t = lane & 3;
    const int wm = wid & 3, wn = wid >> 2;      // 4 M-warps x 2 N-warps
    const int m0 = blockIdx.y * BM;
    const int n0 = blockIdx.x * BN;

    const int nk = K / BK;
    const uint32_t shbase = smem_u32(sh);

    const int lrow0 = tid >> 3;           // +32*i
    const int lchB  = (tid & 7) * 16;
    const int lchH  = (tid & 7) * 8;

    auto issue_tile = [&](int kt) {
        if (kt < nk) {
            uint32_t As = shbase + (uint32_t)(kt % NSTAGE) * STAGE_BYTES;
            uint32_t Bs = As + TILE_BYTES;
            #pragma unroll
            for (int i = 0; i < 4; i++) {
                int row = lrow0 + i * 32;
                int gr = m0 + row;
                cp_async16(As + SW((uint32_t)(row * 128 + lchB)),
                           A + (long long)gr * lda + kt * BK + lchH, gr < M);
                cp_async16(Bs + SW((uint32_t)(row * 128 + lchB)),
                           Bt + (long long)(n0 + row) * K + kt * BK + lchH, true);
            }
        }
        CP_COMMIT();
    };

    float acc[2][8][4];
    #pragma unroll
    for (int i = 0; i < 2; i++)
        #pragma unroll
        for (int j = 0; j < 8; j++)
            #pragma unroll
            for (int q = 0; q < 4; q++) acc[i][j][q] = 0.f;

    issue_tile(0);
    issue_tile(1);

    const int lmRow = lane & 15;
    const int lmHi  = (lane & 16) ? 16 : 0;

    #pragma unroll 1
    for (int kt = 0; kt < nk; ++kt) {
        CP_WAIT(1);
        __syncthreads();
        issue_tile(kt + 2);

        uint32_t As = shbase + (uint32_t)(kt % NSTAGE) * STAGE_BYTES;
        uint32_t Bs = As + TILE_BYTES;

        #pragma unroll
        for (int ks = 0; ks < 4; ++ks) {
            const int kb = ks * 32 + lmHi;
            uint32_t a[2][4], b[8][2];
            #pragma unroll
            for (int mt = 0; mt < 2; ++mt) {
                int row = wm * 32 + mt * 16 + lmRow;
                ldsm_x4(a[mt][0], a[mt][1], a[mt][2], a[mt][3],
                        As + SW((uint32_t)(row * 128 + kb)));
            }
            #pragma unroll
            for (int nq = 0; nq < 4; ++nq) {
                int row = wn * 64 + nq * 16 + lmRow;
                ldsm_x4(b[2*nq][0], b[2*nq+1][0], b[2*nq][1], b[2*nq+1][1],
                        Bs + SW((uint32_t)(row * 128 + kb)));
            }
            #pragma unroll
            for (int mt = 0; mt < 2; ++mt)
                #pragma unroll
                for (int nt = 0; nt < 8; ++nt)
                    mma_f16(acc[mt][nt], a[mt], b[nt]);
        }
    }

    // ---- epilogue: bias + activation + fp16 store ----
    #pragma unroll
    for (int mt = 0; mt < 2; ++mt) {
        int row0 = m0 + wm * 32 + mt * 16 + g;
        #pragma unroll
        for (int nt = 0; nt < 8; ++nt) {
            int col = n0 + wn * 64 + nt * 8 + t * 2;
            float2 bb = *(const float2*)(bias + col);
            float v0 = acc[mt][nt][0] + bb.x;
            float v1 = acc[mt][nt][1] + bb.y;
            float v2 = acc[mt][nt][2] + bb.x;
            float v3 = acc[mt][nt][3] + bb.y;
            if (act == 1) {
                v0 = fmaxf(v0, 0.f); v1 = fmaxf(v1, 0.f);
                v2 = fmaxf(v2, 0.f); v3 = fmaxf(v3, 0.f);
            } else if (act == 2) {
                v0 = (v0 > 0.f) ? v0 : 0.4f * v0;  v1 = (v1 > 0.f) ? v1 : 0.4f * v1;
                v2 = (v2 > 0.f) ? v2 : 0.4f * v2;  v3 = (v3 > 0.f) ? v3 : 0.4f * v3;
            }
            if (row0 < M)
                *(__half2*)(C + (long long)row0 * ldc + col) =
                    __float22half2_rn(make_float2(v0, v1));
            if (row0 + 8 < M)
                *(__half2*)(C + (long long)(row0 + 8) * ldc + col) =
                    __float22half2_rn(make_float2(v2, v3));
        }
    }
}

// ---------------- small GEMM tile (separate copy; used only by small_prep) ----
__device__ void gemm_tile_small(
    const __half* __restrict__ A, int lda,
    const __half* __restrict__ Bt,
    const float* __restrict__ bias,
    __half* __restrict__ C, int ldc,
    int M, int K, int act, int m0, int n0, char* sh)
{
    const int tid = threadIdx.x;
    const int wid = tid >> 5, lane = tid & 31;
    const int g = lane >> 2, t = lane & 3;
    const int wm = wid & 3, wn = wid >> 2;

    const int nk = K / BK;
    const uint32_t shbase = smem_u32(sh);

    const int lrow0 = tid >> 3;
    const int lchB  = (tid & 7) * 16;
    const int lchH  = (tid & 7) * 8;

    auto issue_tile = [&](int kt) {
        if (kt < nk) {
            uint32_t As = shbase + (uint32_t)(kt % NSTAGE) * STAGE_BYTES;
            uint32_t Bs = As + TILE_BYTES;
            #pragma unroll
            for (int i = 0; i < 4; i++) {
                int row = lrow0 + i * 32;
                int gr = m0 + row;
                cp_async16(As + SW((uint32_t)(row * 128 + lchB)),
                           A + (long long)gr * lda + kt * BK + lchH, gr < M);
                cp_async16(Bs + SW((uint32_t)(row * 128 + lchB)),
                           Bt + (long long)(n0 + row) * K + kt * BK + lchH, true);
            }
        }
        CP_COMMIT();
    };

    float acc[2][8][4];
    #pragma unroll
    for (int i = 0; i < 2; i++)
        #pragma unroll
        for (int j = 0; j < 8; j++)
            #pragma unroll
            for (int q = 0; q < 4; q++) acc[i][j][q] = 0.f;

    issue_tile(0);
    issue_tile(1);

    const int lmRow = lane & 15;
    const int lmHi  = (lane & 16) ? 16 : 0;

    #pragma unroll 1
    for (int kt = 0; kt < nk; ++kt) {
        CP_WAIT(1);
        __syncthreads();
        issue_tile(kt + 2);

        uint32_t As = shbase + (uint32_t)(kt % NSTAGE) * STAGE_BYTES;
        uint32_t Bs = As + TILE_BYTES;

        #pragma unroll
        for (int ks = 0; ks < 4; ++ks) {
            const int kb = ks * 32 + lmHi;
            uint32_t a[2][4], b[8][2];
            #pragma unroll
            for (int mt = 0; mt < 2; ++mt) {
                int row = wm * 32 + mt * 16 + lmRow;
                ldsm_x4(a[mt][0], a[mt][1], a[mt][2], a[mt][3],
                        As + SW((uint32_t)(row * 128 + kb)));
            }
            #pragma unroll
            for (int nq = 0; nq < 4; ++nq) {
                int row = wn * 64 + nq * 16 + lmRow;
                ldsm_x4(b[2*nq][0], b[2*nq+1][0], b[2*nq][1], b[2*nq+1][1],
                        Bs + SW((uint32_t)(row * 128 + kb)));
            }
            #pragma unroll
            for (int mt = 0; mt < 2; ++mt)
                #pragma unroll
                for (int nt = 0; nt < 8; ++nt)
                    mma_f16(acc[mt][nt], a[mt], b[nt]);
        }
    }

    #pragma unroll
    for (int mt = 0; mt < 2; ++mt) {
        int row0 = m0 + wm * 32 + mt * 16 + g;
        #pragma unroll
        for (int nt = 0; nt < 8; ++nt) {
            int col = n0 + wn * 64 + nt * 8 + t * 2;
            float2 bb = *(const float2*)(bias + col);
            float v0 = acc[mt][nt][0] + bb.x;
            float v1 = acc[mt][nt][1] + bb.y;
            float v2 = acc[mt][nt][2] + bb.x;
            float v3 = acc[mt][nt][3] + bb.y;
            if (act == 2) {
                v0 = (v0 > 0.f) ? v0 : 0.4f * v0;  v1 = (v1 > 0.f) ? v1 : 0.4f * v1;
                v2 = (v2 > 0.f) ? v2 : 0.4f * v2;  v3 = (v3 > 0.f) ? v3 : 0.4f * v3;
            }
            if (row0 < M)
                *(__half2*)(C + (long long)row0 * ldc + col) =
                    __float22half2_rn(make_float2(v0, v1));
            if (row0 + 8 < M)
                *(__half2*)(C + (long long)(row0 + 8) * ldc + col) =
                    __float22half2_rn(make_float2(v2, v3));
        }
    }
}

// ---------------- small_prep: bias_uv + yp-GEMM + w-GEMM in ONE launch --------
// blocks [0,192):   bias_uv, warp per output n (b_uv[n] = sum_k o2_b[k]*W12[n,k])
// blocks [192,198): n-tile of yp = leaky(yh@py + py_b); epoch-sync; then
//                   same n-tile of w = yp@W3 + pc1_b
__global__ __launch_bounds__(256) void small_prep(
    const __half* __restrict__ wt_W12, const float* __restrict__ o2_b,
    float* __restrict__ buv,
    const __half* __restrict__ yh, const __half* __restrict__ wt_py,
    const float* __restrict__ py_b, __half* __restrict__ yp,
    const __half* __restrict__ wt_W3, const float* __restrict__ pc1_b,
    __half* __restrict__ w)
{
    extern __shared__ char sh[];
    const int bid = blockIdx.x;
    const int tid = threadIdx.x;

    if (bid < 192) {
        int gw = (bid * 256 + tid) >> 5;
        int lane = tid & 31;
        if (gw >= 2 * DD) return;
        const __half2* wrow = (const __half2*)(wt_W12 + (long long)gw * DD);
        float s = 0.f;
        #pragma unroll
        for (int i = lane; i < DD / 2; i += 32) {
            float2 f = __half22float2(wrow[i]);
            s = fmaf(f.x, o2_b[2 * i], s);
            s = fmaf(f.y, o2_b[2 * i + 1], s);
        }
        #pragma unroll
        for (int off = 16; off > 0; off >>= 1)
            s += __shfl_xor_sync(0xffffffffu, s, off);
        if (lane == 0) buv[gw] = s;
        return;
    }

    const int n = bid - 192;   // 0..5
    // yp tile (act=2 leaky)
    gemm_tile_small(yh, DD, wt_py, py_b, yp, DD, GG, DD, 2, 0, n * BN, sh);

    // epoch sync among the 6 GEMM CTAs (monotonic counter; replay-safe, no reset)
    __syncthreads();
    if (tid == 0) {
        __threadfence();
        int old;
        asm volatile("atom.release.gpu.global.add.s32 %0, [%1], 1;"
                     : "=r"(old) : "l"(&g_sync) : "memory");
        int target = old - (old % 6) + 6;
        while (ld_acquire(&g_sync) < target) __nanosleep(64);
    }
    __syncthreads();

    // w tile (act=0)
    gemm_tile_small(yp, DD, wt_W3, pc1_b, w, DD, GG, DD, 0, 0, n * BN, sh);
}

// ---------------- batched prep kernels ----------------------------------------
struct Ptr8 { const float* p[8]; };

// 8x 768x768 transposes: Wt[n*768 + k] = W[k*768 + n], fp16 out
__global__ __launch_bounds__(256) void transpose8(Ptr8 src, __half* dstBase)
{
    const float* W = src.p[blockIdx.z];
    __half* Wt = dstBase + (size_t)blockIdx.z * ((size_t)DD * DD);
    __shared__ float tb[32][33];
    int n0 = blockIdx.x * 32, k0 = blockIdx.y * 32;
    int x = threadIdx.x & 31, y = threadIdx.x >> 5;
    #pragma unroll
    for (int i = 0; i < 32; i += 8)
        tb[y + i][x] = W[(long long)(k0 + y + i) * DD + n0 + x];
    __syncthreads();
    #pragma unroll
    for (int i = 0; i < 32; i += 8)
        Wt[(long long)(n0 + y + i) * DD + k0 + x] = __float2half_rn(tb[x][y + i]);
}

// o1 transpose: [2304(K) x 768(N)] -> Wt[n*2304 + k]
__global__ __launch_bounds__(256) void transpose_o1(
    const float* __restrict__ W, __half* __restrict__ Wt)
{
    __shared__ float tb[32][33];
    int n0 = blockIdx.x * 32, k0 = blockIdx.y * 32;
    int x = threadIdx.x & 31, y = threadIdx.x >> 5;
    #pragma unroll
    for (int i = 0; i < 32; i += 8)
        tb[y + i][x] = W[(long long)(k0 + y + i) * DD + n0 + x];
    __syncthreads();
    #pragma unroll
    for (int i = 0; i < 32; i += 8)
        Wt[(long long)(n0 + y + i) * D3 + k0 + x] = __float2half_rn(tb[x][y + i]);
}

// fp32->fp16 flat convert of x, y, o2_W into xh, yh, o2h
__global__ __launch_bounds__(256) void convert_all(
    const float* __restrict__ x, const float* __restrict__ y,
    const float* __restrict__ o2W,
    __half* __restrict__ xh, __half* __restrict__ yh, __half* __restrict__ o2h)
{
    const long long nx = (long long)NN * DD;
    const long long ny = (long long)GG * DD;
    const long long nw = (long long)DD * DD;
    long long i = ((long long)blockIdx.x * 256 + threadIdx.x) * 4;
    const float* src; __half* dst; long long j;
    if (i < nx) { src = x; dst = xh; j = i; }
    else if (i < nx + ny) { src = y; dst = yh; j = i - nx; }
    else if (i < nx + ny + nw) { src = o2W; dst = o2h; j = i - nx - ny; }
    else return;
    float4 v = *(const float4*)(src + j);
    *(__half2*)(dst + j)     = __float22half2_rn(make_float2(v.x, v.y));
    *(__half2*)(dst + j + 2) = __float22half2_rn(make_float2(v.z, v.w));
}

// ---------------- fused edge head ---------------------------------------------
// per edge: q = relu(u[src] + v[dst] + w[batch[src]]); pred = sigmoid(q@pc2 + b2)
__global__ __launch_bounds__(256) void edge_head(
    const __half* __restrict__ uv, const __half* __restrict__ w,
    const int* __restrict__ edge_index, const int* __restrict__ batch,
    const float* __restrict__ pc2W /*[768,2]*/, const float* __restrict__ b2,
    const float* __restrict__ lab, float* __restrict__ out, int E)
{
    __shared__ float w0[DD];
    __shared__ float w1[DD];
    for (int i = threadIdx.x; i < DD; i += blockDim.x) {
        w0[i] = pc2W[2 * i];
        w1[i] = pc2W[2 * i + 1];
    }
    __syncthreads();

    int warp = threadIdx.x >> 5;
    int lane = threadIdx.x & 31;
    int e = blockIdx.x * 8 + warp;
    if (e >= E) return;

    int src = edge_index[e];
    int dst = edge_index[E + e];
    int gph = batch[src];

    const __half2* ur = (const __half2*)(uv + (long long)src * (2 * DD));
    const __half2* vr = (const __half2*)(uv + (long long)dst * (2 * DD) + DD);
    const __half2* wr = (const __half2*)(w  + (long long)gph * DD);

    float a0 = 0.f, a1 = 0.f;
    #pragma unroll
    for (int i = 0; i < 12; i++) {
        int k = lane + i * 32;               // half2 index, 0..383
        float2 fu = __half22float2(ur[k]);
        float2 fv = __half22float2(vr[k]);
        float2 fw = __half22float2(wr[k]);
        float q0 = fmaxf(fu.x + fv.x + fw.x, 0.f);
        float q1 = fmaxf(fu.y + fv.y + fw.y, 0.f);
        a0 = fmaf(q0, w0[2*k], a0);   a0 = fmaf(q1, w0[2*k+1], a0);
        a1 = fmaf(q0, w1[2*k], a1);   a1 = fmaf(q1, w1[2*k+1], a1);
    }
    #pragma unroll
    for (int off = 16; off > 0; off >>= 1) {
        a0 += __shfl_xor_sync(0xffffffffu, a0, off);
        a1 += __shfl_xor_sync(0xffffffffu, a1, off);
    }
    if (lane == 0) {
        out[2 * e]     = 1.f / (1.f + expf(-(a0 + b2[0])));
        out[2 * e + 1] = 1.f / (1.f + expf(-(a1 + b2[1])));
        out[2 * E + e] = lab[e];
    }
}

// ---------------- host launch ------------------------------------------------
static __half *p_xh = nullptr, *p_h0 = nullptr, *p_emb3 = nullptr, *p_uv = nullptr,
              *p_yh = nullptr, *p_yp = nullptr, *p_w = nullptr, *p_wT = nullptr;
static float  *p_buv = nullptr, *p_zero = nullptr;

extern "C" void kernel_launch(void* const* d_in, const int* in_sizes, int n_in,
                              void* d_out, int out_size)
{
    if (!p_wT) {  // one-time setup on the (uncaptured) correctness call
        cudaGetSymbolAddress((void**)&p_xh,   g_xh);
        cudaGetSymbolAddress((void**)&p_h0,   g_h0);
        cudaGetSymbolAddress((void**)&p_emb3, g_emb3);
        cudaGetSymbolAddress((void**)&p_uv,   g_uv);
        cudaGetSymbolAddress((void**)&p_yh,   g_yh);
        cudaGetSymbolAddress((void**)&p_yp,   g_yp);
        cudaGetSymbolAddress((void**)&p_w,    g_w);
        cudaGetSymbolAddress((void**)&p_wT,   g_wT);
        cudaGetSymbolAddress((void**)&p_buv,  g_buv);
        cudaGetSymbolAddress((void**)&p_zero, g_zero);
        cudaFuncSetAttribute(mma_gemm,
                             cudaFuncAttributeMaxDynamicSharedMemorySize, DYN_BYTES);
        cudaFuncSetAttribute(small_prep,
                             cudaFuncAttributeMaxDynamicSharedMemorySize, DYN_BYTES);
    }

    const float* x          = (const float*)d_in[0];
    const int*   edge_index = (const int*  )d_in[1];
    const int*   batch      = (const int*  )d_in[2];
    const float* y          = (const float*)d_in[5];
    const float* edge_label = (const float*)d_in[6];
    const float* ah_W  = (const float*)d_in[7];
    const float* ah_b  = (const float*)d_in[8];
    const float* c0_W  = (const float*)d_in[9];
    const float* c0_b  = (const float*)d_in[10];
    const float* c1_W  = (const float*)d_in[11];
    const float* c1_b  = (const float*)d_in[12];
    const float* c2_W  = (const float*)d_in[13];
    const float* c2_b  = (const float*)d_in[14];
    const float* o1_W  = (const float*)d_in[15];
    const float* o1_b  = (const float*)d_in[16];
    const float* o2_W  = (const float*)d_in[17];
    const float* o2_b  = (const float*)d_in[18];
    const float* py_W  = (const float*)d_in[19];
    const float* py_b  = (const float*)d_in[20];
    const float* pc1_W = (const float*)d_in[21];
    const float* pc1_b = (const float*)d_in[22];
    const float* pc2_W = (const float*)d_in[23];
    const float* pc2_b = (const float*)d_in[24];

    float* out = (float*)d_out;

    const long long S = (long long)DD * DD;        // 589824
    __half* wt_ah  = p_wT;
    __half* wt_c0  = p_wT + S;
    __half* wt_c1  = p_wT + 2 * S;
    __half* wt_c2  = p_wT + 3 * S;
    __half* wt_py  = p_wT + 4 * S;
    __half* wt_W12 = p_wT + 5 * S;                 // W1|W2 contiguous (M=1536)
    __half* wt_W3  = p_wT + 7 * S;
    __half* wt_o1  = p_wT + 8 * S;                 // [768, 2304]
    __half* wt_uv  = p_wT + 11 * S;                // composite [1536, 768]
    __half* o2h    = p_wT + 13 * S;                // o2_W fp16 row-major

    // ---- prep ----
    {
        Ptr8 s8;
        s8.p[0] = ah_W; s8.p[1] = c0_W; s8.p[2] = c1_W; s8.p[3] = c2_W;
        s8.p[4] = py_W;
        s8.p[5] = pc1_W;                 // W1 = rows 0..767
        s8.p[6] = pc1_W + 768 * DD;      // W2
        s8.p[7] = pc1_W + 1536 * DD;     // W3
        transpose8<<<dim3(DD/32, DD/32, 8), 256>>>(s8, p_wT);
        transpose_o1<<<dim3(DD/32, D3/32), 256>>>(o1_W, wt_o1);
        long long tot = ((long long)NN * DD + (long long)GG * DD + (long long)DD * DD) / 4;
        convert_all<<<(unsigned)((tot + 255) / 256), 256>>>(x, y, o2_W, p_xh, p_yh, o2h);
        // bias_uv + yp + w in one launch (w syncs on yp via epoch counter)
        small_prep<<<198, 256, DYN_BYTES>>>(wt_W12, o2_b, p_buv,
                                            p_yh, wt_py, py_b, p_yp,
                                            wt_W3, pc1_b, p_w);
        // composite weights: rows 0..767 from W1, 768..1535 from W2
        dim3 gC(DD / BN, 2 * DD / BM);    // 6 x 12
        mma_gemm<<<gC, 256, DYN_BYTES>>>(wt_W12, DD, o2h, p_zero, wt_uv, DD, 2 * DD, DD, 0);
    }

    dim3 blk(256);
    dim3 gN(DD / BN, (NN + BM - 1) / BM);        // 6 x 313
    dim3 gUV(2 * DD / BN, (NN + BM - 1) / BM);   // 12 x 313

    // Encoder
    mma_gemm<<<gN, blk, DYN_BYTES>>>(p_xh, DD, wt_ah, ah_b, p_h0, DD, NN, DD, 1);
    mma_gemm<<<gN, blk, DYN_BYTES>>>(p_h0, DD, wt_c0, c0_b, p_emb3, D3, NN, DD, 1);
    mma_gemm<<<gN, blk, DYN_BYTES>>>(p_emb3, D3, wt_c1, c1_b, p_emb3 + DD, D3, NN, DD, 1);
    mma_gemm<<<gN, blk, DYN_BYTES>>>(p_emb3 + DD, D3, wt_c2, c2_b, p_emb3 + 2 * DD, D3, NN, DD, 1);
    mma_gemm<<<gN, blk, DYN_BYTES>>>(p_emb3, D3, wt_o1, o1_b, p_h0, DD, NN, D3, 1);
    // uv = t @ [o2W*W1 | o2W*W2] + b_uv   (o2 folded; emb never materialized)
    mma_gemm<<<gUV, blk, DYN_BYTES>>>(p_h0, DD, wt_uv, p_buv, p_uv, 2 * DD, NN, DD, 0);
    // fused edge head: relu(u+v+w) @ pc2 -> sigmoid -> out; std copy
    edge_head<<<(EE + 7) / 8, 256>>>(p_uv, p_w, edge_index, batch,
                                     pc2_W, pc2_b, edge_label, out, EE);

    (void)n_in; (void)in_sizes; (void)out_size;
}

// round 15
// speedup vs baseline: 1.2945x; 1.0329x over previous
#include <cuda_runtime.h>
#include <cuda_fp16.h>
#include <cstdint>
#include <math.h>

// Problem shapes (fixed by setup_inputs)
#define NN 40000
#define EE 100000
#define DD 768
#define GG 128
#define D3 2304

// ---------------- scratch (static device globals; allocation-free) ----------
__device__ static __half g_xh [(size_t)NN * DD];        // x in fp16
__device__ static __half g_h0 [(size_t)NN * DD];        // h0 / t
__device__ static __half g_emb3[(size_t)NN * D3];       // concat(h1,h2,h3)
__device__ static __half g_uv [(size_t)NN * 2 * DD];    // [u | v] per node
__device__ static __half g_yh [(size_t)GG * DD];        // y in fp16
__device__ static __half g_yp [(size_t)GG * DD];        // leaky(y@py+b)
__device__ static __half g_w  [(size_t)GG * DD];        // yp@W3 + pc1_b per graph
__device__ static __half g_wT [8257536];                // weights: 14 * 768*768 halves
__device__ static float  g_buv[2 * DD];                 // bias for uv GEMM
__device__ static float  g_zero[2 * DD];                // zero bias (device globals zero-init)
__device__ static int    g_sync;                        // epoch counter (never reset)

// ---------------- helpers ----------------------------------------------------
__device__ __forceinline__ uint32_t smem_u32(const void* p) {
    uint32_t a;
    asm("{ .reg .u64 t; cvta.to.shared.u64 t, %1; cvt.u32.u64 %0, t; }" : "=r"(a) : "l"(p));
    return a;
}

__device__ __forceinline__ void cp_async16(uint32_t dst, const void* src, bool pred) {
    int sz = pred ? 16 : 0;
    asm volatile("cp.async.cg.shared.global [%0], [%1], 16, %2;"
                 :: "r"(dst), "l"(src), "r"(sz) : "memory");
}
#define CP_COMMIT() asm volatile("cp.async.commit_group;" ::: "memory")
#define CP_WAIT(n)  asm volatile("cp.async.wait_group %0;" :: "n"(n) : "memory")

__device__ __forceinline__ void ldsm_x4(uint32_t& r0, uint32_t& r1, uint32_t& r2, uint32_t& r3,
                                        uint32_t addr) {
    asm volatile("ldmatrix.sync.aligned.m8n8.x4.shared.b16 {%0,%1,%2,%3}, [%4];"
                 : "=r"(r0), "=r"(r1), "=r"(r2), "=r"(r3) : "r"(addr));
}

__device__ __forceinline__ void mma_f16(float d[4], const uint32_t a[4], const uint32_t b[2]) {
    asm volatile(
        "mma.sync.aligned.m16n8k16.row.col.f32.f16.f16.f32 "
        "{%0,%1,%2,%3}, {%4,%5,%6,%7}, {%8,%9}, {%0,%1,%2,%3};"
        : "+f"(d[0]), "+f"(d[1]), "+f"(d[2]), "+f"(d[3])
        : "r"(a[0]), "r"(a[1]), "r"(a[2]), "r"(a[3]), "r"(b[0]), "r"(b[1]));
}

__device__ __forceinline__ int ld_acquire(const int* p) {
    int v;
    asm volatile("ld.acquire.gpu.global.b32 %0, [%1];" : "=r"(v) : "l"(p) : "memory");
    return v;
}

#define SW(o) ((o) ^ (((o) >> 3) & 0x70))   // SW128 byte swizzle within 1KB atom

// ---------------- fp16 mma.sync GEMM (R5/R8 proven config + m-offset) ---------
// C[M,N] = act(A[M,K] @ Bt[N,K]^T + bias),  A/Bt/C fp16, bias fp32, accum fp32.
// BM=128, BN=128, BK=64 halves (128B rows, SW128). 8 warps: 4M x 2N (32x64 tile).
// mOffBlk: m-block offset (row-split dual-stream pipelining).
#define BM 128
#define BN 128
#define BK 64
#define TILE_BYTES 16384                   // 128 rows * 128B
#define STAGE_BYTES (2 * TILE_BYTES)       // A then B: 32 KB
#define NSTAGE 3
#define DYN_BYTES (NSTAGE * STAGE_BYTES)   // 96 KB -> 2 CTAs/SM

__global__ __launch_bounds__(256) void mma_gemm(
    const __half* __restrict__ A, int lda,
    const __half* __restrict__ Bt,
    const float* __restrict__ bias,
    __half* __restrict__ C, int ldc,
    int M, int K, int act, int mOffBlk)
{
    extern __shared__ char sh[];

    const int tid = threadIdx.x;
    const int wid = tid >> 5, lane = tid & 31;
    const int g = lane >> 2, t = lane & 3;
    const int wm = wid & 3, wn = wid >> 2;      // 4 M-warps x 2 N-warps
    const int m0 = (blockIdx.y + mOffBlk) * BM;
    const int n0 = blockIdx.x * BN;

    const int nk = K / BK;
    const uint32_t shbase = smem_u32(sh);

    const int lrow0 = tid >> 3;           // +32*i
    const int lchB  = (tid & 7) * 16;
    const int lchH  = (tid & 7) * 8;

    auto issue_tile = [&](int kt) {
        if (kt < nk) {
            uint32_t As = shbase + (uint32_t)(kt % NSTAGE) * STAGE_BYTES;
            uint32_t Bs = As + TILE_BYTES;
            #pragma unroll
            for (int i = 0; i < 4; i++) {
                int row = lrow0 + i * 32;
                int gr = m0 + row;
                cp_async16(As + SW((uint32_t)(row * 128 + lchB)),
                           A + (long long)gr * lda + kt * BK + lchH, gr < M);
                cp_async16(Bs + SW((uint32_t)(row * 128 + lchB)),
                           Bt + (long long)(n0 + row) * K + kt * BK + lchH, true);
            }
        }
        CP_COMMIT();
    };

    float acc[2][8][4];
    #pragma unroll
    for (int i = 0; i < 2; i++)
        #pragma unroll
        for (int j = 0; j < 8; j++)
            #pragma unroll
            for (int q = 0; q < 4; q++) acc[i][j][q] = 0.f;

    issue_tile(0);
    issue_tile(1);

    const int lmRow = lane & 15;
    const int lmHi  = (lane & 16) ? 16 : 0;

    #pragma unroll 1
    for (int kt = 0; kt < nk; ++kt) {
        CP_WAIT(1);
        __syncthreads();
        issue_tile(kt + 2);

        uint32_t As = shbase + (uint32_t)(kt % NSTAGE) * STAGE_BYTES;
        uint32_t Bs = As + TILE_BYTES;

        #pragma unroll
        for (int ks = 0; ks < 4; ++ks) {
            const int kb = ks * 32 + lmHi;
            uint32_t a[2][4], b[8][2];
            #pragma unroll
            for (int mt = 0; mt < 2; ++mt) {
                int row = wm * 32 + mt * 16 + lmRow;
                ldsm_x4(a[mt][0], a[mt][1], a[mt][2], a[mt][3],
                        As + SW((uint32_t)(row * 128 + kb)));
            }
            #pragma unroll
            for (int nq = 0; nq < 4; ++nq) {
                int row = wn * 64 + nq * 16 + lmRow;
                ldsm_x4(b[2*nq][0], b[2*nq+1][0], b[2*nq][1], b[2*nq+1][1],
                        Bs + SW((uint32_t)(row * 128 + kb)));
            }
            #pragma unroll
            for (int mt = 0; mt < 2; ++mt)
                #pragma unroll
                for (int nt = 0; nt < 8; ++nt)
                    mma_f16(acc[mt][nt], a[mt], b[nt]);
        }
    }

    // ---- epilogue: bias + activation + fp16 store ----
    #pragma unroll
    for (int mt = 0; mt < 2; ++mt) {
        int row0 = m0 + wm * 32 + mt * 16 + g;
        #pragma unroll
        for (int nt = 0; nt < 8; ++nt) {
            int col = n0 + wn * 64 + nt * 8 + t * 2;
            float2 bb = *(const float2*)(bias + col);
            float v0 = acc[mt][nt][0] + bb.x;
            float v1 = acc[mt][nt][1] + bb.y;
            float v2 = acc[mt][nt][2] + bb.x;
            float v3 = acc[mt][nt][3] + bb.y;
            if (act == 1) {
                v0 = fmaxf(v0, 0.f); v1 = fmaxf(v1, 0.f);
                v2 = fmaxf(v2, 0.f); v3 = fmaxf(v3, 0.f);
            } else if (act == 2) {
                v0 = (v0 > 0.f) ? v0 : 0.4f * v0;  v1 = (v1 > 0.f) ? v1 : 0.4f * v1;
                v2 = (v2 > 0.f) ? v2 : 0.4f * v2;  v3 = (v3 > 0.f) ? v3 : 0.4f * v3;
            }
            if (row0 < M)
                *(__half2*)(C + (long long)row0 * ldc + col) =
                    __float22half2_rn(make_float2(v0, v1));
            if (row0 + 8 < M)
                *(__half2*)(C + (long long)(row0 + 8) * ldc + col) =
                    __float22half2_rn(make_float2(v2, v3));
        }
    }
}

// ---------------- small GEMM tile (separate copy; used only by small_prep) ----
__device__ void gemm_tile_small(
    const __half* __restrict__ A, int lda,
    const __half* __restrict__ Bt,
    const float* __restrict__ bias,
    __half* __restrict__ C, int ldc,
    int M, int K, int act, int m0, int n0, char* sh)
{
    const int tid = threadIdx.x;
    const int wid = tid >> 5, lane = tid & 31;
    const int g = lane >> 2, t = lane & 3;
    const int wm = wid & 3, wn = wid >> 2;

    const int nk = K / BK;
    const uint32_t shbase = smem_u32(sh);

    const int lrow0 = tid >> 3;
    const int lchB  = (tid & 7) * 16;
    const int lchH  = (tid & 7) * 8;

    auto issue_tile = [&](int kt) {
        if (kt < nk) {
            uint32_t As = shbase + (uint32_t)(kt % NSTAGE) * STAGE_BYTES;
            uint32_t Bs = As + TILE_BYTES;
            #pragma unroll
            for (int i = 0; i < 4; i++) {
                int row = lrow0 + i * 32;
                int gr = m0 + row;
                cp_async16(As + SW((uint32_t)(row * 128 + lchB)),
                           A + (long long)gr * lda + kt * BK + lchH, gr < M);
                cp_async16(Bs + SW((uint32_t)(row * 128 + lchB)),
                           Bt + (long long)(n0 + row) * K + kt * BK + lchH, true);
            }
        }
        CP_COMMIT();
    };

    float acc[2][8][4];
    #pragma unroll
    for (int i = 0; i < 2; i++)
        #pragma unroll
        for (int j = 0; j < 8; j++)
            #pragma unroll
            for (int q = 0; q < 4; q++) acc[i][j][q] = 0.f;

    issue_tile(0);
    issue_tile(1);

    const int lmRow = lane & 15;
    const int lmHi  = (lane & 16) ? 16 : 0;

    #pragma unroll 1
    for (int kt = 0; kt < nk; ++kt) {
        CP_WAIT(1);
        __syncthreads();
        issue_tile(kt + 2);

        uint32_t As = shbase + (uint32_t)(kt % NSTAGE) * STAGE_BYTES;
        uint32_t Bs = As + TILE_BYTES;

        #pragma unroll
        for (int ks = 0; ks < 4; ++ks) {
            const int kb = ks * 32 + lmHi;
            uint32_t a[2][4], b[8][2];
            #pragma unroll
            for (int mt = 0; mt < 2; ++mt) {
                int row = wm * 32 + mt * 16 + lmRow;
                ldsm_x4(a[mt][0], a[mt][1], a[mt][2], a[mt][3],
                        As + SW((uint32_t)(row * 128 + kb)));
            }
            #pragma unroll
            for (int nq = 0; nq < 4; ++nq) {
                int row = wn * 64 + nq * 16 + lmRow;
                ldsm_x4(b[2*nq][0], b[2*nq+1][0], b[2*nq][1], b[2*nq+1][1],
                        Bs + SW((uint32_t)(row * 128 + kb)));
            }
            #pragma unroll
            for (int mt = 0; mt < 2; ++mt)
                #pragma unroll
                for (int nt = 0; nt < 8; ++nt)
                    mma_f16(acc[mt][nt], a[mt], b[nt]);
        }
    }

    #pragma unroll
    for (int mt = 0; mt < 2; ++mt) {
        int row0 = m0 + wm * 32 + mt * 16 + g;
        #pragma unroll
        for (int nt = 0; nt < 8; ++nt) {
            int col = n0 + wn * 64 + nt * 8 + t * 2;
            float2 bb = *(const float2*)(bias + col);
            float v0 = acc[mt][nt][0] + bb.x;
            float v1 = acc[mt][nt][1] + bb.y;
            float v2 = acc[mt][nt][2] + bb.x;
            float v3 = acc[mt][nt][3] + bb.y;
            if (act == 2) {
                v0 = (v0 > 0.f) ? v0 : 0.4f * v0;  v1 = (v1 > 0.f) ? v1 : 0.4f * v1;
                v2 = (v2 > 0.f) ? v2 : 0.4f * v2;  v3 = (v3 > 0.f) ? v3 : 0.4f * v3;
            }
            if (row0 < M)
                *(__half2*)(C + (long long)row0 * ldc + col) =
                    __float22half2_rn(make_float2(v0, v1));
            if (row0 + 8 < M)
                *(__half2*)(C + (long long)(row0 + 8) * ldc + col) =
                    __float22half2_rn(make_float2(v2, v3));
        }
    }
}

// ---------------- small_prep: bias_uv + yp-GEMM + w-GEMM in ONE launch --------
__global__ __launch_bounds__(256) void small_prep(
    const __half* __restrict__ wt_W12, const float* __restrict__ o2_b,
    float* __restrict__ buv,
    const __half* __restrict__ yh, const __half* __restrict__ wt_py,
    const float* __restrict__ py_b, __half* __restrict__ yp,
    const __half* __restrict__ wt_W3, const float* __restrict__ pc1_b,
    __half* __restrict__ w)
{
    extern __shared__ char sh[];
    const int bid = blockIdx.x;
    const int tid = threadIdx.x;

    if (bid < 192) {
        int gw = (bid * 256 + tid) >> 5;
        int lane = tid & 31;
        if (gw >= 2 * DD) return;
        const __half2* wrow = (const __half2*)(wt_W12 + (long long)gw * DD);
        float s = 0.f;
        #pragma unroll
        for (int i = lane; i < DD / 2; i += 32) {
            float2 f = __half22float2(wrow[i]);
            s = fmaf(f.x, o2_b[2 * i], s);
            s = fmaf(f.y, o2_b[2 * i + 1], s);
        }
        #pragma unroll
        for (int off = 16; off > 0; off >>= 1)
            s += __shfl_xor_sync(0xffffffffu, s, off);
        if (lane == 0) buv[gw] = s;
        return;
    }

    const int n = bid - 192;   // 0..5
    gemm_tile_small(yh, DD, wt_py, py_b, yp, DD, GG, DD, 2, 0, n * BN, sh);

    // epoch sync among the 6 GEMM CTAs (monotonic counter; replay-safe, no reset)
    __syncthreads();
    if (tid == 0) {
        __threadfence();
        int old;
        asm volatile("atom.release.gpu.global.add.s32 %0, [%1], 1;"
                     : "=r"(old) : "l"(&g_sync) : "memory");
        int target = old - (old % 6) + 6;
        while (ld_acquire(&g_sync) < target) __nanosleep(64);
    }
    __syncthreads();

    gemm_tile_small(yp, DD, wt_W3, pc1_b, w, DD, GG, DD, 0, 0, n * BN, sh);
}

// ---------------- batched prep kernels ----------------------------------------
struct Ptr8 { const float* p[8]; };

__global__ __launch_bounds__(256) void transpose8(Ptr8 src, __half* dstBase)
{
    const float* W = src.p[blockIdx.z];
    __half* Wt = dstBase + (size_t)blockIdx.z * ((size_t)DD * DD);
    __shared__ float tb[32][33];
    int n0 = blockIdx.x * 32, k0 = blockIdx.y * 32;
    int x = threadIdx.x & 31, y = threadIdx.x >> 5;
    #pragma unroll
    for (int i = 0; i < 32; i += 8)
        tb[y + i][x] = W[(long long)(k0 + y + i) * DD + n0 + x];
    __syncthreads();
    #pragma unroll
    for (int i = 0; i < 32; i += 8)
        Wt[(long long)(n0 + y + i) * DD + k0 + x] = __float2half_rn(tb[x][y + i]);
}

__global__ __launch_bounds__(256) void transpose_o1(
    const float* __restrict__ W, __half* __restrict__ Wt)
{
    __shared__ float tb[32][33];
    int n0 = blockIdx.x * 32, k0 = blockIdx.y * 32;
    int x = threadIdx.x & 31, y = threadIdx.x >> 5;
    #pragma unroll
    for (int i = 0; i < 32; i += 8)
        tb[y + i][x] = W[(long long)(k0 + y + i) * DD + n0 + x];
    __syncthreads();
    #pragma unroll
    for (int i = 0; i < 32; i += 8)
        Wt[(long long)(n0 + y + i) * D3 + k0 + x] = __float2half_rn(tb[x][y + i]);
}

__global__ __launch_bounds__(256) void convert_all(
    const float* __restrict__ x, const float* __restrict__ y,
    const float* __restrict__ o2W,
    __half* __restrict__ xh, __half* __restrict__ yh, __half* __restrict__ o2h)
{
    const long long nx = (long long)NN * DD;
    const long long ny = (long long)GG * DD;
    const long long nw = (long long)DD * DD;
    long long i = ((long long)blockIdx.x * 256 + threadIdx.x) * 4;
    const float* src; __half* dst; long long j;
    if (i < nx) { src = x; dst = xh; j = i; }
    else if (i < nx + ny) { src = y; dst = yh; j = i - nx; }
    else if (i < nx + ny + nw) { src = o2W; dst = o2h; j = i - nx - ny; }
    else return;
    float4 v = *(const float4*)(src + j);
    *(__half2*)(dst + j)     = __float22half2_rn(make_float2(v.x, v.y));
    *(__half2*)(dst + j + 2) = __float22half2_rn(make_float2(v.z, v.w));
}

// ---------------- fused edge head ---------------------------------------------
__global__ __launch_bounds__(256) void edge_head(
    const __half* __restrict__ uv, const __half* __restrict__ w,
    const int* __restrict__ edge_index, const int* __restrict__ batch,
    const float* __restrict__ pc2W /*[768,2]*/, const float* __restrict__ b2,
    const float* __restrict__ lab, float* __restrict__ out, int E)
{
    __shared__ float w0[DD];
    __shared__ float w1[DD];
    for (int i = threadIdx.x; i < DD; i += blockDim.x) {
        w0[i] = pc2W[2 * i];
        w1[i] = pc2W[2 * i + 1];
    }
    __syncthreads();

    int warp = threadIdx.x >> 5;
    int lane = threadIdx.x & 31;
    int e = blockIdx.x * 8 + warp;
    if (e >= E) return;

    int src = edge_index[e];
    int dst = edge_index[E + e];
    int gph = batch[src];

    const __half2* ur = (const __half2*)(uv + (long long)src * (2 * DD));
    const __half2* vr = (const __half2*)(uv + (long long)dst * (2 * DD) + DD);
    const __half2* wr = (const __half2*)(w  + (long long)gph * DD);

    float a0 = 0.f, a1 = 0.f;
    #pragma unroll
    for (int i = 0; i < 12; i++) {
        int k = lane + i * 32;
        float2 fu = __half22float2(ur[k]);
        float2 fv = __half22float2(vr[k]);
        float2 fw = __half22float2(wr[k]);
        float q0 = fmaxf(fu.x + fv.x + fw.x, 0.f);
        float q1 = fmaxf(fu.y + fv.y + fw.y, 0.f);
        a0 = fmaf(q0, w0[2*k], a0);   a0 = fmaf(q1, w0[2*k+1], a0);
        a1 = fmaf(q0, w1[2*k], a1);   a1 = fmaf(q1, w1[2*k+1], a1);
    }
    #pragma unroll
    for (int off = 16; off > 0; off >>= 1) {
        a0 += __shfl_xor_sync(0xffffffffu, a0, off);
        a1 += __shfl_xor_sync(0xffffffffu, a1, off);
    }
    if (lane == 0) {
        out[2 * e]     = 1.f / (1.f + expf(-(a0 + b2[0])));
        out[2 * e + 1] = 1.f / (1.f + expf(-(a1 + b2[1])));
        out[2 * E + e] = lab[e];
    }
}

// ---------------- host launch ------------------------------------------------
static __half *p_xh = nullptr, *p_h0 = nullptr, *p_emb3 = nullptr, *p_uv = nullptr,
              *p_yh = nullptr, *p_yp = nullptr, *p_w = nullptr, *p_wT = nullptr;
static float  *p_buv = nullptr, *p_zero = nullptr;
static cudaStream_t s_side = nullptr;
static cudaEvent_t evPrep = nullptr, evSide = nullptr, evB = nullptr;

// m-block split: 313 blocks -> 157 (A, main stream) + 156 (B, side stream)
#define MB_TOT 313
#define MB_A   157
#define MB_B   (MB_TOT - MB_A)

extern "C" void kernel_launch(void* const* d_in, const int* in_sizes, int n_in,
                              void* d_out, int out_size)
{
    if (!p_wT) {  // one-time setup on the (uncaptured) correctness call
        cudaGetSymbolAddress((void**)&p_xh,   g_xh);
        cudaGetSymbolAddress((void**)&p_h0,   g_h0);
        cudaGetSymbolAddress((void**)&p_emb3, g_emb3);
        cudaGetSymbolAddress((void**)&p_uv,   g_uv);
        cudaGetSymbolAddress((void**)&p_yh,   g_yh);
        cudaGetSymbolAddress((void**)&p_yp,   g_yp);
        cudaGetSymbolAddress((void**)&p_w,    g_w);
        cudaGetSymbolAddress((void**)&p_wT,   g_wT);
        cudaGetSymbolAddress((void**)&p_buv,  g_buv);
        cudaGetSymbolAddress((void**)&p_zero, g_zero);
        cudaFuncSetAttribute(mma_gemm,
                             cudaFuncAttributeMaxDynamicSharedMemorySize, DYN_BYTES);
        cudaFuncSetAttribute(small_prep,
                             cudaFuncAttributeMaxDynamicSharedMemorySize, DYN_BYTES);
        cudaStreamCreateWithFlags(&s_side, cudaStreamNonBlocking);
        cudaEventCreateWithFlags(&evPrep, cudaEventDisableTiming);
        cudaEventCreateWithFlags(&evSide, cudaEventDisableTiming);
        cudaEventCreateWithFlags(&evB,    cudaEventDisableTiming);
    }

    const float* x          = (const float*)d_in[0];
    const int*   edge_index = (const int*  )d_in[1];
    const int*   batch      = (const int*  )d_in[2];
    const float* y          = (const float*)d_in[5];
    const float* edge_label = (const float*)d_in[6];
    const float* ah_W  = (const float*)d_in[7];
    const float* ah_b  = (const float*)d_in[8];
    const float* c0_W  = (const float*)d_in[9];
    const float* c0_b  = (const float*)d_in[10];
    const float* c1_W  = (const float*)d_in[11];
    const float* c1_b  = (const float*)d_in[12];
    const float* c2_W  = (const float*)d_in[13];
    const float* c2_b  = (const float*)d_in[14];
    const float* o1_W  = (const float*)d_in[15];
    const float* o1_b  = (const float*)d_in[16];
    const float* o2_W  = (const float*)d_in[17];
    const float* o2_b  = (const float*)d_in[18];
    const float* py_W  = (const float*)d_in[19];
    const float* py_b  = (const float*)d_in[20];
    const float* pc1_W = (const float*)d_in[21];
    const float* pc1_b = (const float*)d_in[22];
    const float* pc2_W = (const float*)d_in[23];
    const float* pc2_b = (const float*)d_in[24];

    float* out = (float*)d_out;

    const long long S = (long long)DD * DD;        // 589824
    __half* wt_ah  = p_wT;
    __half* wt_c0  = p_wT + S;
    __half* wt_c1  = p_wT + 2 * S;
    __half* wt_c2  = p_wT + 3 * S;
    __half* wt_py  = p_wT + 4 * S;
    __half* wt_W12 = p_wT + 5 * S;                 // W1|W2 contiguous (M=1536)
    __half* wt_W3  = p_wT + 7 * S;
    __half* wt_o1  = p_wT + 8 * S;                 // [768, 2304]
    __half* wt_uv  = p_wT + 11 * S;                // composite [1536, 768]
    __half* o2h    = p_wT + 13 * S;                // o2_W fp16 row-major

    dim3 blk(256);

    // ---- prep on main stream ----
    {
        Ptr8 s8;
        s8.p[0] = ah_W; s8.p[1] = c0_W; s8.p[2] = c1_W; s8.p[3] = c2_W;
        s8.p[4] = py_W;
        s8.p[5] = pc1_W;                 // W1 = rows 0..767
        s8.p[6] = pc1_W + 768 * DD;      // W2
        s8.p[7] = pc1_W + 1536 * DD;     // W3
        transpose8<<<dim3(DD/32, DD/32, 8), blk>>>(s8, p_wT);
        transpose_o1<<<dim3(DD/32, D3/32), blk>>>(o1_W, wt_o1);
        long long tot = ((long long)NN * DD + (long long)GG * DD + (long long)DD * DD) / 4;
        convert_all<<<(unsigned)((tot + 255) / 256), blk>>>(x, y, o2_W, p_xh, p_yh, o2h);
    }
    cudaEventRecord(evPrep, 0);

    // ---- side stream: small_prep + composite GEMM + half-B chain ----
    cudaStreamWaitEvent(s_side, evPrep, 0);
    small_prep<<<198, blk, DYN_BYTES, s_side>>>(wt_W12, o2_b, p_buv,
                                                p_yh, wt_py, py_b, p_yp,
                                                wt_W3, pc1_b, p_w);
    mma_gemm<<<dim3(DD/BN, 2*DD/BM), blk, DYN_BYTES, s_side>>>(
        wt_W12, DD, o2h, p_zero, wt_uv, DD, 2*DD, DD, 0, 0);
    cudaEventRecord(evSide, s_side);   // buv, wt_uv, w ready

    dim3 gA(DD / BN, MB_A);        // half A: m-blocks [0,157)
    dim3 gB(DD / BN, MB_B);        // half B: m-blocks [157,313)
    dim3 gA2(2*DD / BN, MB_A);     // uv half A
    dim3 gB2(2*DD / BN, MB_B);     // uv half B

    // half-B chain on side stream (row-wise independent of half A)
    mma_gemm<<<gB, blk, DYN_BYTES, s_side>>>(p_xh, DD, wt_ah, ah_b, p_h0, DD, NN, DD, 1, MB_A);
    mma_gemm<<<gB, blk, DYN_BYTES, s_side>>>(p_h0, DD, wt_c0, c0_b, p_emb3, D3, NN, DD, 1, MB_A);
    mma_gemm<<<gB, blk, DYN_BYTES, s_side>>>(p_emb3, D3, wt_c1, c1_b, p_emb3 + DD, D3, NN, DD, 1, MB_A);
    mma_gemm<<<gB, blk, DYN_BYTES, s_side>>>(p_emb3 + DD, D3, wt_c2, c2_b, p_emb3 + 2*DD, D3, NN, DD, 1, MB_A);
    mma_gemm<<<gB, blk, DYN_BYTES, s_side>>>(p_emb3, D3, wt_o1, o1_b, p_h0, DD, NN, D3, 1, MB_A);
    mma_gemm<<<gB2, blk, DYN_BYTES, s_side>>>(p_h0, DD, wt_uv, p_buv, p_uv, 2*DD, NN, DD, 0, MB_A);
    cudaEventRecord(evB, s_side);

    // half-A chain on main stream
    mma_gemm<<<gA, blk, DYN_BYTES>>>(p_xh, DD, wt_ah, ah_b, p_h0, DD, NN, DD, 1, 0);
    mma_gemm<<<gA, blk, DYN_BYTES>>>(p_h0, DD, wt_c0, c0_b, p_emb3, D3, NN, DD, 1, 0);
    mma_gemm<<<gA, blk, DYN_BYTES>>>(p_emb3, D3, wt_c1, c1_b, p_emb3 + DD, D3, NN, DD, 1, 0);
    mma_gemm<<<gA, blk, DYN_BYTES>>>(p_emb3 + DD, D3, wt_c2, c2_b, p_emb3 + 2*DD, D3, NN, DD, 1, 0);
    mma_gemm<<<gA, blk, DYN_BYTES>>>(p_emb3, D3, wt_o1, o1_b, p_h0, DD, NN, D3, 1, 0);
    cudaStreamWaitEvent(0, evSide, 0);   // uv_A needs buv + wt_uv
    mma_gemm<<<gA2, blk, DYN_BYTES>>>(p_h0, DD, wt_uv, p_buv, p_uv, 2*DD, NN, DD, 0, 0);

    // join: edge_head needs uv (both halves) + w (side, ordered before evB)
    cudaStreamWaitEvent(0, evB, 0);
    edge_head<<<(EE + 7) / 8, blk>>>(p_uv, p_w, edge_index, batch,
                                     pc2_W, pc2_b, edge_label, out, EE);

    (void)n_in; (void)in_sizes; (void)out_size;
}